// round 10
// baseline (speedup 1.0000x reference)
#include <cuda_runtime.h>
#include <cuda_bf16.h>
#include <math.h>

// ---------------- problem constants ----------------
#define NN    8192
#define EE    262144
#define INC   64
#define OUTC  64
#define GG    64
#define NCLS  10
#define DIN   192
#define DOUT  192
#define D3    576
#define D2    384
#define BNEPS 1e-5f

#define NBLK  148
#define NTHR  1024
#define NT    (NBLK * NTHR)

// ---------------- device scratch ----------------
__device__ int   g_flags[2];
__device__ int   g_deg[NN];
__device__ float g_dinv[NN];
__device__ int   g_offs[NN + 1];
__device__ int   g_cnt[NN];
__device__ int   g_col[EE];
__device__ float g_wt[EE];
__device__ float g_Hab[NN * 128];     // [Lx | L^2 x], ld=128
__device__ float g_H[NN * DOUT];
__device__ float g_Wm[DOUT * DIN];
__device__ float g_bnsum[DOUT];
__device__ float g_bnsq[DOUT];
__device__ int   g_seg[GG + 1];
__device__ float g_Hg[GG * D3];
__device__ int   g_barcnt = 0;
__device__ volatile int g_bargen = 0;

__device__ __forceinline__ int fetch_idx(const void* p, long long i, int is32) {
    if (is32) return ((const int*)p)[i];
    return (int)(((const long long*)p)[i]);
}

// generation grid barrier; nblk co-resident blocks required
__device__ __forceinline__ void gridbar(int nblk) {
    __syncthreads();
    if (threadIdx.x == 0) {
        int gen = g_bargen;
        __threadfence();
        if (atomicAdd(&g_barcnt, 1) == nblk - 1) {
            g_barcnt = 0;
            __threadfence();
            g_bargen = gen + 1;
        } else {
            while (g_bargen == gen) { __nanosleep(32); }
        }
        __threadfence();
    }
    __syncthreads();
}

// SpMM: out = in - sum_e w_e * in[col_e], warp per node, grid-stride
__device__ __forceinline__ void spmm_dev(const float* __restrict__ in, int ldin,
                                         float* __restrict__ out, int ldout, int gtid) {
    int w = gtid >> 5;
    int lane = gtid & 31;
    for (int node = w; node < NN; node += NT / 32) {
        int p = g_offs[node];
        int pe = g_offs[node + 1];
        float acc0 = 0.f, acc1 = 0.f;
        for (; p + 4 <= pe; p += 4) {
            int c0 = g_col[p], c1 = g_col[p + 1], c2 = g_col[p + 2], c3 = g_col[p + 3];
            float w0 = g_wt[p], w1 = g_wt[p + 1], w2 = g_wt[p + 2], w3 = g_wt[p + 3];
            const float* r0 = in + (long)c0 * ldin;
            const float* r1 = in + (long)c1 * ldin;
            const float* r2 = in + (long)c2 * ldin;
            const float* r3 = in + (long)c3 * ldin;
            acc0 += w0 * r0[lane] + w1 * r1[lane] + w2 * r2[lane] + w3 * r3[lane];
            acc1 += w0 * r0[lane + 32] + w1 * r1[lane + 32] + w2 * r2[lane + 32] + w3 * r3[lane + 32];
        }
        for (; p < pe; p++) {
            int c0 = g_col[p];
            float w0 = g_wt[p];
            const float* r0 = in + (long)c0 * ldin;
            acc0 += w0 * r0[lane];
            acc1 += w0 * r0[lane + 32];
        }
        const float* ri = in + (long)node * ldin;
        out[(long)node * ldout + lane]      = ri[lane]      - acc0;
        out[(long)node * ldout + lane + 32] = ri[lane + 32] - acc1;
    }
}

// ================= K1: persistent build + SpMM x2 =================
__global__ void __launch_bounds__(NTHR, 1)
build_kernel(const float* __restrict__ x, const void* ei, const void* batch,
             const float* __restrict__ W, const float* __restrict__ u) {
    __shared__ int   s_int[32];
    __shared__ float s_v[DIN];
    __shared__ float s_red[DOUT];
    __shared__ float s_scal[2];

    int b = blockIdx.x, t = threadIdx.x;
    int gtid = b * NTHR + t;

    // ---- P0: zero + flags/segments (block 0) + sigma/Wm (block 147) ----
    for (int i = gtid; i < NN; i += NT) { g_deg[i] = 0; g_cnt[i] = 0; }
    if (gtid < DOUT) { g_bnsum[gtid] = 0.f; g_bnsq[gtid] = 0.f; }

    if (b == 0) {
        if (t < 32) {
            // dtype probes: int64 view, high word of spread elements (in-bounds either way)
            const int* e32 = (const int*)ei;
            int bad = (e32[2 * ((long long)t * (EE / 32)) + 1] != 0);
            unsigned m = __ballot_sync(0xffffffffu, bad);
            const int* bb = (const int*)batch;
            int badb = (bb[2 * ((long long)t * (NN / 64)) + 1] != 0);
            unsigned mb = __ballot_sync(0xffffffffu, badb);
            if (t == 0) { g_flags[0] = m ? 1 : 0; g_flags[1] = mb ? 1 : 0; }
        }
        __syncthreads();
        if (t <= GG) {
            if (t == GG) g_seg[GG] = NN;
            else {
                int is32 = g_flags[1];
                int lo = 0, hi = NN;
                while (lo < hi) {
                    int mid = (lo + hi) >> 1;
                    if (fetch_idx(batch, mid, is32) < t) lo = mid + 1; else hi = mid;
                }
                g_seg[t] = lo;
            }
        }
    }
    if (b == NBLK - 1) {
        // spectral sigma (one power-iteration step) + masked scaled Wm
        if (t < DIN) {
            float vt = 0.f;
            for (int i = 0; i < DOUT; i++) vt += W[i * DIN + t] * u[i];
            s_v[t] = vt;
        }
        __syncthreads();
        if (t == 0) {
            float s = 0.f;
            for (int k = 0; k < DIN; k++) s += s_v[k] * s_v[k];
            s_scal[0] = sqrtf(s) + 1e-12f;
        }
        __syncthreads();
        if (t < DIN) s_v[t] = s_v[t] / s_scal[0];
        __syncthreads();
        if (t < DOUT) {
            float wv = 0.f;
            for (int j = 0; j < DIN; j++) wv += W[(long)t * DIN + j] * s_v[j];
            s_red[t] = u[t] * wv;
        }
        __syncthreads();
        if (t == 0) {
            float s = 0.f;
            for (int k = 0; k < DOUT; k++) s += s_red[k];
            s_scal[1] = 1.0f / s;
        }
        __syncthreads();
        if (t < DOUT) {
            float is = s_scal[1];
            int kmax = INC * (t / OUTC + 1);
            const float* wr = W + (long)t * DIN;
            float* wo = g_Wm + (long)t * DIN;
            for (int c = 0; c < DIN; c++) wo[c] = (c < kmax) ? wr[c] * is : 0.f;
        }
    }
    gridbar(NBLK);

    // ---- P1: degree histogram ----
    {
        int is32 = g_flags[0];
        for (int e = gtid; e < EE; e += NT)
            atomicAdd(&g_deg[fetch_idx(ei, e, is32)], 1);
    }
    gridbar(NBLK);

    // ---- P2: exclusive scan + dinv (block 0) ----
    if (b == 0) {
        int lane = t & 31, wid = t >> 5;
        int base = t * 8;
        int d[8], loc[8];
        int run = 0;
#pragma unroll
        for (int k = 0; k < 8; k++) { d[k] = g_deg[base + k]; loc[k] = run; run += d[k]; }
        int v = run;
#pragma unroll
        for (int o = 1; o < 32; o <<= 1) {
            int n = __shfl_up_sync(0xffffffffu, v, o);
            if (lane >= o) v += n;
        }
        if (lane == 31) s_int[wid] = v;
        __syncthreads();
        if (wid == 0) {
            int w = s_int[lane];
#pragma unroll
            for (int o = 1; o < 32; o <<= 1) {
                int n = __shfl_up_sync(0xffffffffu, w, o);
                if (lane >= o) w += n;
            }
            s_int[lane] = w;
        }
        __syncthreads();
        int warpoff = (wid > 0) ? s_int[wid - 1] : 0;
        int excl = warpoff + v - run;
#pragma unroll
        for (int k = 0; k < 8; k++) {
            g_offs[base + k] = excl + loc[k];
            g_dinv[base + k] = (d[k] > 0) ? rsqrtf((float)d[k]) : 0.f;
        }
        if (t == NTHR - 1) g_offs[NN] = warpoff + v;
    }
    gridbar(NBLK);

    // ---- P3: scatter edges + per-edge weights ----
    {
        int is32 = g_flags[0];
        for (int e = gtid; e < EE; e += NT) {
            int r = fetch_idx(ei, e, is32);
            int c = fetch_idx(ei, (long long)EE + e, is32);
            int pos = g_offs[r] + atomicAdd(&g_cnt[r], 1);
            g_col[pos] = c;
            g_wt[pos] = g_dinv[r] * g_dinv[c];
        }
    }
    gridbar(NBLK);

    // ---- P4/P5: SpMM x2 ----
    spmm_dev(x, INC, g_Hab, 128, gtid);
    gridbar(NBLK);
    spmm_dev(g_Hab, 128, g_Hab + 64, 128, gtid);
}

// ================= K2: GEMM H = [x|Hab] @ Wm^T + b, kmax per n-tile, fused BN1 stats ========
__global__ void gemm_kernel(const float* __restrict__ x, const float* __restrict__ bias) {
    __shared__ float As[16][65];
    __shared__ float Bs[16][65];
    __shared__ float ssum[16][68];
    __shared__ float ssq[16][68];
    int t  = threadIdx.x;                 // 256
    int tx = t & 15, ty = t >> 4;
    int m0 = blockIdx.x * 64;
    int n0 = blockIdx.y * 64;
    int kmax = 64 * (blockIdx.y + 1);     // block-lower-triangular mask
    int lm = t >> 2;
    int lk = (t & 3) * 4;
    float cr[4][4];
#pragma unroll
    for (int i = 0; i < 4; i++)
#pragma unroll
        for (int j = 0; j < 4; j++) cr[i][j] = 0.f;

    for (int k0 = 0; k0 < kmax; k0 += 16) {
        float4 av;
        if (k0 < 64) av = *(const float4*)(x + (long)(m0 + lm) * INC + k0 + lk);
        else         av = *(const float4*)(g_Hab + (long)(m0 + lm) * 128 + (k0 - 64) + lk);
        As[lk + 0][lm] = av.x; As[lk + 1][lm] = av.y; As[lk + 2][lm] = av.z; As[lk + 3][lm] = av.w;
        float4 bv = *(const float4*)(g_Wm + (long)(n0 + lm) * DIN + k0 + lk);
        Bs[lk + 0][lm] = bv.x; Bs[lk + 1][lm] = bv.y; Bs[lk + 2][lm] = bv.z; Bs[lk + 3][lm] = bv.w;
        __syncthreads();
#pragma unroll
        for (int kk = 0; kk < 16; kk++) {
            float a0 = As[kk][ty * 4 + 0], a1 = As[kk][ty * 4 + 1];
            float a2 = As[kk][ty * 4 + 2], a3 = As[kk][ty * 4 + 3];
            float b0 = Bs[kk][tx * 4 + 0], b1 = Bs[kk][tx * 4 + 1];
            float b2 = Bs[kk][tx * 4 + 2], b3 = Bs[kk][tx * 4 + 3];
            cr[0][0] += a0 * b0; cr[0][1] += a0 * b1; cr[0][2] += a0 * b2; cr[0][3] += a0 * b3;
            cr[1][0] += a1 * b0; cr[1][1] += a1 * b1; cr[1][2] += a1 * b2; cr[1][3] += a1 * b3;
            cr[2][0] += a2 * b0; cr[2][1] += a2 * b1; cr[2][2] += a2 * b2; cr[2][3] += a2 * b3;
            cr[3][0] += a3 * b0; cr[3][1] += a3 * b1; cr[3][2] += a3 * b2; cr[3][3] += a3 * b3;
        }
        __syncthreads();
    }
    float psum[4] = {0, 0, 0, 0}, psq[4] = {0, 0, 0, 0};
#pragma unroll
    for (int j = 0; j < 4; j++) {
        int n = n0 + tx * 4 + j;
        float bj = bias[n];
#pragma unroll
        for (int i = 0; i < 4; i++) {
            int m = m0 + ty * 4 + i;
            float v = cr[i][j] + bj;
            g_H[(long)m * DOUT + n] = v;
            psum[j] += v; psq[j] += v * v;
        }
    }
#pragma unroll
    for (int j = 0; j < 4; j++) { ssum[ty][tx * 4 + j] = psum[j]; ssq[ty][tx * 4 + j] = psq[j]; }
    __syncthreads();
    if (t < 64) {
        float s = 0.f, q = 0.f;
#pragma unroll
        for (int yy = 0; yy < 16; yy++) { s += ssum[yy][t]; q += ssq[yy][t]; }
        atomicAdd(&g_bnsum[n0 + t], s);
        atomicAdd(&g_bnsq[n0 + t], q);
    }
}

// ================= K3: pool + head (persistent 64 blocks x 768) =================
__global__ void __launch_bounds__(768, 1)
pool_head_kernel(const float* __restrict__ g1, const float* __restrict__ be1,
                 const float* __restrict__ g2, const float* __restrict__ be2,
                 const float* __restrict__ w1, const float* __restrict__ b1,
                 const float* __restrict__ w2, const float* __restrict__ b2,
                 const float* __restrict__ w3, const float* __restrict__ b3,
                 float* __restrict__ out) {
    __shared__ float sh[4 * D3 + 4 * D2 + 4 * DOUT];   // head buffers (4608 floats)
    __shared__ float sa[DOUT], sc[DOUT];
    __shared__ float ps[4][DOUT], pm[4][DOUT];

    int b = blockIdx.x, t = threadIdx.x;   // 64 x 768

    // ---- pool: BN1 apply + avg|sum|max per graph ----
    {
        int j = t % DOUT, y = t / DOUT;    // y in 0..3
        if (y == 0) {
            float mu = g_bnsum[j] * (1.f / NN);
            float var = g_bnsq[j] * (1.f / NN) - mu * mu;
            float a = g1[j] * rsqrtf(var + BNEPS);
            sa[j] = a;
            sc[j] = be1[j] - a * mu;
        }
        __syncthreads();
        int s0 = g_seg[b], e0 = g_seg[b + 1];
        float a = sa[j], c = sc[j];
        float sum = 0.f, mx = -INFINITY;
        for (int r = s0 + y; r < e0; r += 4) {
            float v = a * g_H[(long)r * DOUT + j] + c;
            sum += v;
            mx = fmaxf(mx, v);
        }
        ps[y][j] = sum; pm[y][j] = mx;
        __syncthreads();
        if (y == 0) {
            float ts = ps[0][j] + ps[1][j] + ps[2][j] + ps[3][j];
            float tm = fmaxf(fmaxf(pm[0][j], pm[1][j]), fmaxf(pm[2][j], pm[3][j]));
            float cnt = fmaxf((float)(e0 - s0), 1.f);
            g_Hg[b * D3 + j]            = ts / cnt;
            g_Hg[b * D3 + DOUT + j]     = ts;
            g_Hg[b * D3 + 2 * DOUT + j] = tm;
        }
    }
    gridbar(GG);

    // ---- head: BN2 + FC1(relu) + FC2(relu) + FC3 + log_softmax, 4 graphs per block ----
    if (b < GG / 4) {
        float* xr = sh;                    // [4][D3]
        float* f1 = sh + 4 * D3;           // [4][D2]
        float* f2 = f1 + 4 * D2;           // [4][DOUT]
        int g0 = b * 4;
        for (int ch = t; ch < D3; ch += 768) {
            float s = 0.f, q = 0.f;
#pragma unroll 4
            for (int r = 0; r < GG; r++) {
                float v = g_Hg[r * D3 + ch];
                s += v; q += v * v;
            }
            float mu = s * (1.f / GG);
            float var = q * (1.f / GG) - mu * mu;
            float a = g2[ch] * rsqrtf(var + BNEPS);
            float c = be2[ch] - a * mu;
#pragma unroll
            for (int gi = 0; gi < 4; gi++)
                xr[gi * D3 + ch] = a * g_Hg[(g0 + gi) * D3 + ch] + c;
        }
        __syncthreads();
        if (t < D2) {
            float acc0 = b1[t], acc1 = acc0, acc2 = acc0, acc3 = acc0;
            const float* wr = w1 + (long)t * D3;
#pragma unroll 4
            for (int k = 0; k < D3; k++) {
                float w = wr[k];
                acc0 += w * xr[k]; acc1 += w * xr[D3 + k];
                acc2 += w * xr[2 * D3 + k]; acc3 += w * xr[3 * D3 + k];
            }
            f1[t] = fmaxf(acc0, 0.f); f1[D2 + t] = fmaxf(acc1, 0.f);
            f1[2 * D2 + t] = fmaxf(acc2, 0.f); f1[3 * D2 + t] = fmaxf(acc3, 0.f);
        }
        __syncthreads();
        if (t < DOUT) {
            float acc0 = b2[t], acc1 = acc0, acc2 = acc0, acc3 = acc0;
            const float* wr = w2 + (long)t * D2;
#pragma unroll 4
            for (int k = 0; k < D2; k++) {
                float w = wr[k];
                acc0 += w * f1[k]; acc1 += w * f1[D2 + k];
                acc2 += w * f1[2 * D2 + k]; acc3 += w * f1[3 * D2 + k];
            }
            f2[t] = fmaxf(acc0, 0.f); f2[DOUT + t] = fmaxf(acc1, 0.f);
            f2[2 * DOUT + t] = fmaxf(acc2, 0.f); f2[3 * DOUT + t] = fmaxf(acc3, 0.f);
        }
        __syncthreads();
        int wid = t >> 5, lane = t & 31;
        if (wid < 4) {
            float logit = -INFINITY;
            if (lane < NCLS) {
                float acc = b3[lane];
                const float* wr = w3 + lane * DOUT;
                for (int k = 0; k < DOUT; k++) acc += f2[wid * DOUT + k] * wr[k];
                logit = acc;
            }
            float mx = logit;
#pragma unroll
            for (int o = 16; o > 0; o >>= 1) mx = fmaxf(mx, __shfl_xor_sync(0xffffffffu, mx, o));
            float ex = (lane < NCLS) ? expf(logit - mx) : 0.f;
            float se = ex;
#pragma unroll
            for (int o = 16; o > 0; o >>= 1) se += __shfl_xor_sync(0xffffffffu, se, o);
            if (lane < NCLS) out[(g0 + wid) * NCLS + lane] = logit - mx - logf(se);
        }
    }
}

// ---------------- launch ----------------
extern "C" void kernel_launch(void* const* d_in, const int* in_sizes, int n_in,
                              void* d_out, int out_size) {
    const float* x      = (const float*)d_in[0];
    const void*  ei     = d_in[1];
    const void*  batch  = d_in[2];
    const float* W_orig = (const float*)d_in[3];
    const float* bb     = (const float*)d_in[4];
    const float* u      = (const float*)d_in[5];
    const float* bn1g   = (const float*)d_in[6];
    const float* bn1b   = (const float*)d_in[7];
    const float* bn2g   = (const float*)d_in[8];
    const float* bn2b   = (const float*)d_in[9];
    const float* w1     = (const float*)d_in[10];
    const float* b1     = (const float*)d_in[11];
    const float* w2     = (const float*)d_in[12];
    const float* b2     = (const float*)d_in[13];
    const float* w3     = (const float*)d_in[14];
    const float* b3     = (const float*)d_in[15];
    float* out = (float*)d_out;

    build_kernel<<<NBLK, NTHR>>>(x, ei, batch, W_orig, u);
    dim3 ggrid(NN / 64, DOUT / 64);
    gemm_kernel<<<ggrid, 256>>>(x, bb);
    pool_head_kernel<<<GG, 768>>>(bn1g, bn1b, bn2g, bn2b, w1, b1, w2, b2, w3, b3, out);
}

// round 11
// speedup vs baseline: 1.0356x; 1.0356x over previous
#include <cuda_runtime.h>
#include <cuda_bf16.h>
#include <math.h>

// ---------------- problem constants ----------------
#define NN    8192
#define EE    262144
#define INC   64
#define OUTC  64
#define GG    64
#define NCLS  10
#define DIN   192
#define DOUT  192
#define D3    576
#define D2    384
#define BNEPS 1e-5f

#define NBLK  148
#define NTHR  1024
#define NT    (NBLK * NTHR)

// ---------------- device scratch ----------------
__device__ int   g_flags[2];
__device__ int   g_deg[NN];
__device__ float g_dinv[NN];
__device__ int   g_offs[NN + 1];
__device__ int   g_cnt[NN];
__device__ int   g_col[EE];
__device__ float g_wt[EE];
__device__ float g_Hab[NN * 128];     // [Lx | L^2 x], ld=128
__device__ float g_H[NN * DOUT];
__device__ float g_Wm[DOUT * DIN];
__device__ float g_bnsum[DOUT];
__device__ float g_bnsq[DOUT];
__device__ int   g_seg[GG + 1];
__device__ float g_Hg[GG * D3];
__device__ int   g_barcnt = 0;
__device__ volatile int g_bargen = 0;

__device__ __forceinline__ int fetch_idx(const void* p, long long i, int is32) {
    if (is32) return ((const int*)p)[i];
    return (int)(((const long long*)p)[i]);
}

// generation grid barrier; nblk co-resident blocks required
__device__ __forceinline__ void gridbar(int nblk) {
    __syncthreads();
    if (threadIdx.x == 0) {
        int gen = g_bargen;
        __threadfence();
        if (atomicAdd(&g_barcnt, 1) == nblk - 1) {
            g_barcnt = 0;
            __threadfence();
            g_bargen = gen + 1;
        } else {
            while (g_bargen == gen) { __nanosleep(32); }
        }
        __threadfence();
    }
    __syncthreads();
}

// ================= K1: persistent prep (graph build + sigma/Wm) =================
__global__ void __launch_bounds__(NTHR, 1)
prep_kernel(const void* ei, const void* batch,
            const float* __restrict__ W, const float* __restrict__ u) {
    __shared__ int   s_int[32];
    __shared__ float s_v[DIN];
    __shared__ float s_red[DOUT];
    __shared__ float s_scal[2];

    int b = blockIdx.x, t = threadIdx.x;
    int gtid = b * NTHR + t;

    // ---- P0: zero + flags/segments (block 0) + sigma/Wm (block 147) ----
    for (int i = gtid; i < NN; i += NT) { g_deg[i] = 0; g_cnt[i] = 0; }
    if (gtid < DOUT) { g_bnsum[gtid] = 0.f; g_bnsq[gtid] = 0.f; }

    if (b == 0) {
        if (t < 32) {
            // dtype probes: int64 view, high word of spread elements (in-bounds either way)
            const int* e32 = (const int*)ei;
            int bad = (e32[2 * ((long long)t * (EE / 32)) + 1] != 0);
            unsigned m = __ballot_sync(0xffffffffu, bad);
            const int* bb = (const int*)batch;
            int badb = (bb[2 * ((long long)t * (NN / 64)) + 1] != 0);
            unsigned mb = __ballot_sync(0xffffffffu, badb);
            if (t == 0) { g_flags[0] = m ? 1 : 0; g_flags[1] = mb ? 1 : 0; }
        }
        __syncthreads();
        if (t <= GG) {
            if (t == GG) g_seg[GG] = NN;
            else {
                int is32 = g_flags[1];
                int lo = 0, hi = NN;
                while (lo < hi) {
                    int mid = (lo + hi) >> 1;
                    if (fetch_idx(batch, mid, is32) < t) lo = mid + 1; else hi = mid;
                }
                g_seg[t] = lo;
            }
        }
    }
    if (b == NBLK - 1) {
        // spectral sigma (one power-iteration step) + masked scaled Wm
        if (t < DIN) {
            float vt = 0.f;
            for (int i = 0; i < DOUT; i++) vt += W[i * DIN + t] * u[i];
            s_v[t] = vt;
        }
        __syncthreads();
        if (t == 0) {
            float s = 0.f;
            for (int k = 0; k < DIN; k++) s += s_v[k] * s_v[k];
            s_scal[0] = sqrtf(s) + 1e-12f;
        }
        __syncthreads();
        if (t < DIN) s_v[t] = s_v[t] / s_scal[0];
        __syncthreads();
        if (t < DOUT) {
            float wv = 0.f;
            for (int j = 0; j < DIN; j++) wv += W[(long)t * DIN + j] * s_v[j];
            s_red[t] = u[t] * wv;
        }
        __syncthreads();
        if (t == 0) {
            float s = 0.f;
            for (int k = 0; k < DOUT; k++) s += s_red[k];
            s_scal[1] = 1.0f / s;
        }
        __syncthreads();
        if (t < DOUT) {
            float is = s_scal[1];
            int kmax = INC * (t / OUTC + 1);
            const float* wr = W + (long)t * DIN;
            float* wo = g_Wm + (long)t * DIN;
            for (int c = 0; c < DIN; c++) wo[c] = (c < kmax) ? wr[c] * is : 0.f;
        }
    }
    gridbar(NBLK);

    // ---- P1: degree histogram ----
    {
        int is32 = g_flags[0];
        for (int e = gtid; e < EE; e += NT)
            atomicAdd(&g_deg[fetch_idx(ei, e, is32)], 1);
    }
    gridbar(NBLK);

    // ---- P2: exclusive scan + dinv (block 0) ----
    if (b == 0) {
        int lane = t & 31, wid = t >> 5;
        int base = t * 8;
        int d[8], loc[8];
        int run = 0;
#pragma unroll
        for (int k = 0; k < 8; k++) { d[k] = g_deg[base + k]; loc[k] = run; run += d[k]; }
        int v = run;
#pragma unroll
        for (int o = 1; o < 32; o <<= 1) {
            int n = __shfl_up_sync(0xffffffffu, v, o);
            if (lane >= o) v += n;
        }
        if (lane == 31) s_int[wid] = v;
        __syncthreads();
        if (wid == 0) {
            int w = s_int[lane];
#pragma unroll
            for (int o = 1; o < 32; o <<= 1) {
                int n = __shfl_up_sync(0xffffffffu, w, o);
                if (lane >= o) w += n;
            }
            s_int[lane] = w;
        }
        __syncthreads();
        int warpoff = (wid > 0) ? s_int[wid - 1] : 0;
        int excl = warpoff + v - run;
#pragma unroll
        for (int k = 0; k < 8; k++) {
            g_offs[base + k] = excl + loc[k];
            g_dinv[base + k] = (d[k] > 0) ? rsqrtf((float)d[k]) : 0.f;
        }
        if (t == NTHR - 1) g_offs[NN] = warpoff + v;
    }
    gridbar(NBLK);

    // ---- P3: scatter edges + per-edge weights ----
    {
        int is32 = g_flags[0];
        for (int e = gtid; e < EE; e += NT) {
            int r = fetch_idx(ei, e, is32);
            int c = fetch_idx(ei, (long long)EE + e, is32);
            int pos = g_offs[r] + atomicAdd(&g_cnt[r], 1);
            g_col[pos] = c;
            g_wt[pos] = g_dinv[r] * g_dinv[c];
        }
    }
}

// ================= K2/K3: SpMM  out = in - sum_e w_e in[col_e] (warp/node, high occ) ==========
__global__ void spmm_kernel(const float* __restrict__ in, int ldin,
                            float* __restrict__ out, int ldout) {
    int gtid = blockIdx.x * blockDim.x + threadIdx.x;
    int node = gtid >> 5;
    int lane = gtid & 31;
    if (node >= NN) return;
    int p = g_offs[node];
    int pe = g_offs[node + 1];
    float acc0 = 0.f, acc1 = 0.f;
    for (; p + 4 <= pe; p += 4) {
        int c0 = g_col[p], c1 = g_col[p + 1], c2 = g_col[p + 2], c3 = g_col[p + 3];
        float w0 = g_wt[p], w1 = g_wt[p + 1], w2 = g_wt[p + 2], w3 = g_wt[p + 3];
        const float* r0 = in + (long)c0 * ldin;
        const float* r1 = in + (long)c1 * ldin;
        const float* r2 = in + (long)c2 * ldin;
        const float* r3 = in + (long)c3 * ldin;
        acc0 += w0 * r0[lane] + w1 * r1[lane] + w2 * r2[lane] + w3 * r3[lane];
        acc1 += w0 * r0[lane + 32] + w1 * r1[lane + 32] + w2 * r2[lane + 32] + w3 * r3[lane + 32];
    }
    for (; p < pe; p++) {
        int c0 = g_col[p];
        float w0 = g_wt[p];
        const float* r0 = in + (long)c0 * ldin;
        acc0 += w0 * r0[lane];
        acc1 += w0 * r0[lane + 32];
    }
    const float* ri = in + (long)node * ldin;
    out[(long)node * ldout + lane]      = ri[lane]      - acc0;
    out[(long)node * ldout + lane + 32] = ri[lane + 32] - acc1;
}

// ================= K4 (profiled): GEMM H = [x|Hab] @ Wm^T + b, float4 LDS, fused BN1 stats ====
__global__ void gemm_kernel(const float* __restrict__ x, const float* __restrict__ bias) {
    __shared__ float As[16][64];
    __shared__ float Bs[16][64];
    __shared__ float ssum[16][68];
    __shared__ float ssq[16][68];
    int t  = threadIdx.x;                 // 256
    int tx = t & 15, ty = t >> 4;
    int m0 = blockIdx.x * 64;
    int n0 = blockIdx.y * 64;
    int kmax = 64 * (blockIdx.y + 1);     // block-lower-triangular mask
    int lm = t >> 2;
    int lk = (t & 3) * 4;
    float cr[4][4];
#pragma unroll
    for (int i = 0; i < 4; i++)
#pragma unroll
        for (int j = 0; j < 4; j++) cr[i][j] = 0.f;

    for (int k0 = 0; k0 < kmax; k0 += 16) {
        float4 av;
        if (k0 < 64) av = *(const float4*)(x + (long)(m0 + lm) * INC + k0 + lk);
        else         av = *(const float4*)(g_Hab + (long)(m0 + lm) * 128 + (k0 - 64) + lk);
        As[lk + 0][lm] = av.x; As[lk + 1][lm] = av.y; As[lk + 2][lm] = av.z; As[lk + 3][lm] = av.w;
        float4 bv = *(const float4*)(g_Wm + (long)(n0 + lm) * DIN + k0 + lk);
        Bs[lk + 0][lm] = bv.x; Bs[lk + 1][lm] = bv.y; Bs[lk + 2][lm] = bv.z; Bs[lk + 3][lm] = bv.w;
        __syncthreads();
#pragma unroll
        for (int kk = 0; kk < 16; kk++) {
            float4 a = *(const float4*)&As[kk][ty * 4];
            float4 bq = *(const float4*)&Bs[kk][tx * 4];
            cr[0][0] += a.x * bq.x; cr[0][1] += a.x * bq.y; cr[0][2] += a.x * bq.z; cr[0][3] += a.x * bq.w;
            cr[1][0] += a.y * bq.x; cr[1][1] += a.y * bq.y; cr[1][2] += a.y * bq.z; cr[1][3] += a.y * bq.w;
            cr[2][0] += a.z * bq.x; cr[2][1] += a.z * bq.y; cr[2][2] += a.z * bq.z; cr[2][3] += a.z * bq.w;
            cr[3][0] += a.w * bq.x; cr[3][1] += a.w * bq.y; cr[3][2] += a.w * bq.z; cr[3][3] += a.w * bq.w;
        }
        __syncthreads();
    }
    float psum[4] = {0, 0, 0, 0}, psq[4] = {0, 0, 0, 0};
#pragma unroll
    for (int j = 0; j < 4; j++) {
        int n = n0 + tx * 4 + j;
        float bj = bias[n];
#pragma unroll
        for (int i = 0; i < 4; i++) {
            int m = m0 + ty * 4 + i;
            float v = cr[i][j] + bj;
            g_H[(long)m * DOUT + n] = v;
            psum[j] += v; psq[j] += v * v;
        }
    }
#pragma unroll
    for (int j = 0; j < 4; j++) { ssum[ty][tx * 4 + j] = psum[j]; ssq[ty][tx * 4 + j] = psq[j]; }
    __syncthreads();
    if (t < 64) {
        float s = 0.f, q = 0.f;
#pragma unroll
        for (int yy = 0; yy < 16; yy++) { s += ssum[yy][t]; q += ssq[yy][t]; }
        atomicAdd(&g_bnsum[n0 + t], s);
        atomicAdd(&g_bnsq[n0 + t], q);
    }
}

// ================= K5: pool + head (persistent 64 blocks x 768) =================
__global__ void __launch_bounds__(768, 1)
pool_head_kernel(const float* __restrict__ g1, const float* __restrict__ be1,
                 const float* __restrict__ g2, const float* __restrict__ be2,
                 const float* __restrict__ w1, const float* __restrict__ b1,
                 const float* __restrict__ w2, const float* __restrict__ b2,
                 const float* __restrict__ w3, const float* __restrict__ b3,
                 float* __restrict__ out) {
    __shared__ float sh[4 * D3 + 4 * D2 + 4 * DOUT];
    __shared__ float sa[DOUT], sc[DOUT];
    __shared__ float ps[4][DOUT], pm[4][DOUT];

    int b = blockIdx.x, t = threadIdx.x;   // 64 x 768

    // ---- pool: BN1 apply + avg|sum|max per graph ----
    {
        int j = t % DOUT, y = t / DOUT;
        if (y == 0) {
            float mu = g_bnsum[j] * (1.f / NN);
            float var = g_bnsq[j] * (1.f / NN) - mu * mu;
            float a = g1[j] * rsqrtf(var + BNEPS);
            sa[j] = a;
            sc[j] = be1[j] - a * mu;
        }
        __syncthreads();
        int s0 = g_seg[b], e0 = g_seg[b + 1];
        float a = sa[j], c = sc[j];
        float sum = 0.f, mx = -INFINITY;
        for (int r = s0 + y; r < e0; r += 4) {
            float v = a * g_H[(long)r * DOUT + j] + c;
            sum += v;
            mx = fmaxf(mx, v);
        }
        ps[y][j] = sum; pm[y][j] = mx;
        __syncthreads();
        if (y == 0) {
            float ts = ps[0][j] + ps[1][j] + ps[2][j] + ps[3][j];
            float tm = fmaxf(fmaxf(pm[0][j], pm[1][j]), fmaxf(pm[2][j], pm[3][j]));
            float cnt = fmaxf((float)(e0 - s0), 1.f);
            g_Hg[b * D3 + j]            = ts / cnt;
            g_Hg[b * D3 + DOUT + j]     = ts;
            g_Hg[b * D3 + 2 * DOUT + j] = tm;
        }
    }
    gridbar(GG);

    // ---- head: BN2 + FC1(relu) + FC2(relu) + FC3 + log_softmax, 4 graphs per block ----
    if (b < GG / 4) {
        float* xr = sh;                    // [4][D3]
        float* f1 = sh + 4 * D3;           // [4][D2]
        float* f2 = f1 + 4 * D2;           // [4][DOUT]
        int g0 = b * 4;
        for (int ch = t; ch < D3; ch += 768) {
            float s = 0.f, q = 0.f;
#pragma unroll 4
            for (int r = 0; r < GG; r++) {
                float v = g_Hg[r * D3 + ch];
                s += v; q += v * v;
            }
            float mu = s * (1.f / GG);
            float var = q * (1.f / GG) - mu * mu;
            float a = g2[ch] * rsqrtf(var + BNEPS);
            float c = be2[ch] - a * mu;
#pragma unroll
            for (int gi = 0; gi < 4; gi++)
                xr[gi * D3 + ch] = a * g_Hg[(g0 + gi) * D3 + ch] + c;
        }
        __syncthreads();
        if (t < D2) {
            float acc0 = b1[t], acc1 = acc0, acc2 = acc0, acc3 = acc0;
            const float* wr = w1 + (long)t * D3;
#pragma unroll 4
            for (int k = 0; k < D3; k++) {
                float w = wr[k];
                acc0 += w * xr[k]; acc1 += w * xr[D3 + k];
                acc2 += w * xr[2 * D3 + k]; acc3 += w * xr[3 * D3 + k];
            }
            f1[t] = fmaxf(acc0, 0.f); f1[D2 + t] = fmaxf(acc1, 0.f);
            f1[2 * D2 + t] = fmaxf(acc2, 0.f); f1[3 * D2 + t] = fmaxf(acc3, 0.f);
        }
        __syncthreads();
        if (t < DOUT) {
            float acc0 = b2[t], acc1 = acc0, acc2 = acc0, acc3 = acc0;
            const float* wr = w2 + (long)t * D2;
#pragma unroll 4
            for (int k = 0; k < D2; k++) {
                float w = wr[k];
                acc0 += w * f1[k]; acc1 += w * f1[D2 + k];
                acc2 += w * f1[2 * D2 + k]; acc3 += w * f1[3 * D2 + k];
            }
            f2[t] = fmaxf(acc0, 0.f); f2[DOUT + t] = fmaxf(acc1, 0.f);
            f2[2 * DOUT + t] = fmaxf(acc2, 0.f); f2[3 * DOUT + t] = fmaxf(acc3, 0.f);
        }
        __syncthreads();
        int wid = t >> 5, lane = t & 31;
        if (wid < 4) {
            float logit = -INFINITY;
            if (lane < NCLS) {
                float acc = b3[lane];
                const float* wr = w3 + lane * DOUT;
                for (int k = 0; k < DOUT; k++) acc += f2[wid * DOUT + k] * wr[k];
                logit = acc;
            }
            float mx = logit;
#pragma unroll
            for (int o = 16; o > 0; o >>= 1) mx = fmaxf(mx, __shfl_xor_sync(0xffffffffu, mx, o));
            float ex = (lane < NCLS) ? expf(logit - mx) : 0.f;
            float se = ex;
#pragma unroll
            for (int o = 16; o > 0; o >>= 1) se += __shfl_xor_sync(0xffffffffu, se, o);
            if (lane < NCLS) out[(g0 + wid) * NCLS + lane] = logit - mx - logf(se);
        }
    }
}

// ---------------- launch ----------------
extern "C" void kernel_launch(void* const* d_in, const int* in_sizes, int n_in,
                              void* d_out, int out_size) {
    const float* x      = (const float*)d_in[0];
    const void*  ei     = d_in[1];
    const void*  batch  = d_in[2];
    const float* W_orig = (const float*)d_in[3];
    const float* bb     = (const float*)d_in[4];
    const float* u      = (const float*)d_in[5];
    const float* bn1g   = (const float*)d_in[6];
    const float* bn1b   = (const float*)d_in[7];
    const float* bn2g   = (const float*)d_in[8];
    const float* bn2b   = (const float*)d_in[9];
    const float* w1     = (const float*)d_in[10];
    const float* b1     = (const float*)d_in[11];
    const float* w2     = (const float*)d_in[12];
    const float* b2     = (const float*)d_in[13];
    const float* w3     = (const float*)d_in[14];
    const float* b3     = (const float*)d_in[15];
    float* out = (float*)d_out;

    float* hab = nullptr;
    cudaGetSymbolAddress((void**)&hab, g_Hab);

    prep_kernel<<<NBLK, NTHR>>>(ei, batch, W_orig, u);                 // launch 1
    spmm_kernel<<<NN * 32 / 256, 256>>>(x, INC, hab, 128);             // launch 2
    spmm_kernel<<<NN * 32 / 256, 256>>>(hab, 128, hab + 64, 128);      // launch 3
    dim3 ggrid(NN / 64, DOUT / 64);
    gemm_kernel<<<ggrid, 256>>>(x, bb);                                // launch 4 (profiled)
    pool_head_kernel<<<GG, 768>>>(bn1g, bn1b, bn2g, bn2b, w1, b1, w2, b2, w3, b3, out);
}

// round 12
// speedup vs baseline: 1.0617x; 1.0252x over previous
#include <cuda_runtime.h>
#include <cuda_bf16.h>
#include <math.h>

// ---------------- problem constants ----------------
#define NN    8192
#define EE    262144
#define INC   64
#define OUTC  64
#define GG    64
#define NCLS  10
#define DIN   192
#define DOUT  192
#define D3    576
#define D2    384
#define BNEPS 1e-5f

#define NBLK  148
#define NTHR  1024
#define NT    (NBLK * NTHR)

// ---------------- device scratch ----------------
__device__ int   g_flags[2];
__device__ int   g_deg[NN];
__device__ float g_dinv[NN];
__device__ int   g_offs[NN + 1];
__device__ int   g_cnt[NN];
__device__ int   g_col[EE];
__device__ float g_wt[EE];
__device__ float g_Hab[NN * 128];     // [Lx | L^2 x], ld=128
__device__ float g_H[NN * DOUT];
__device__ float g_Wm[DOUT * DIN];
__device__ float g_bnsum[DOUT];
__device__ float g_bnsq[DOUT];
__device__ int   g_seg[GG + 1];
__device__ float g_Hg[GG * D3];
__device__ float g_psum[GG * 4 * DOUT];   // pool partials (4 row-quarters per graph)
__device__ float g_pmax[GG * 4 * DOUT];
__device__ int   g_barcnt = 0;
__device__ volatile int g_bargen = 0;

__device__ __forceinline__ int fetch_idx(const void* p, long long i, int is32) {
    if (is32) return ((const int*)p)[i];
    return (int)(((const long long*)p)[i]);
}

// generation grid barrier; nblk co-resident blocks required
__device__ __forceinline__ void gridbar(int nblk) {
    __syncthreads();
    if (threadIdx.x == 0) {
        int gen = g_bargen;
        __threadfence();
        if (atomicAdd(&g_barcnt, 1) == nblk - 1) {
            g_barcnt = 0;
            __threadfence();
            g_bargen = gen + 1;
        } else {
            while (g_bargen == gen) { __nanosleep(32); }
        }
        __threadfence();
    }
    __syncthreads();
}

// SpMM body: out = in - sum_e w_e in[col_e], warp/node, grid-stride over nwarp
__device__ __forceinline__ void spmm_body(const float* __restrict__ in, int ldin,
                                          float* __restrict__ out, int ldout,
                                          int warp, int lane, int nwarp) {
    for (int node = warp; node < NN; node += nwarp) {
        int p = g_offs[node];
        int pe = g_offs[node + 1];
        float acc0 = 0.f, acc1 = 0.f;
        for (; p + 4 <= pe; p += 4) {
            int c0 = g_col[p], c1 = g_col[p + 1], c2 = g_col[p + 2], c3 = g_col[p + 3];
            float w0 = g_wt[p], w1 = g_wt[p + 1], w2 = g_wt[p + 2], w3 = g_wt[p + 3];
            const float* r0 = in + (long)c0 * ldin;
            const float* r1 = in + (long)c1 * ldin;
            const float* r2 = in + (long)c2 * ldin;
            const float* r3 = in + (long)c3 * ldin;
            acc0 += w0 * r0[lane] + w1 * r1[lane] + w2 * r2[lane] + w3 * r3[lane];
            acc1 += w0 * r0[lane + 32] + w1 * r1[lane + 32] + w2 * r2[lane + 32] + w3 * r3[lane + 32];
        }
        for (; p < pe; p++) {
            int c0 = g_col[p];
            float w0 = g_wt[p];
            const float* r0 = in + (long)c0 * ldin;
            acc0 += w0 * r0[lane];
            acc1 += w0 * r0[lane + 32];
        }
        const float* ri = in + (long)node * ldin;
        out[(long)node * ldout + lane]      = ri[lane]      - acc0;
        out[(long)node * ldout + lane + 32] = ri[lane + 32] - acc1;
    }
}

// ================= K1: persistent prep (graph build + sigma/Wm + SpMM1) =================
__global__ void __launch_bounds__(NTHR, 1)
prep_kernel(const float* __restrict__ x, const void* ei, const void* batch,
            const float* __restrict__ W, const float* __restrict__ u) {
    __shared__ int   s_int[32];
    __shared__ float s_v[DIN];
    __shared__ float s_red[DOUT];
    __shared__ float s_scal[2];

    int b = blockIdx.x, t = threadIdx.x;
    int gtid = b * NTHR + t;

    // ---- P0: zero + flags/segments (block 0) + sigma/Wm (block 147) ----
    for (int i = gtid; i < NN; i += NT) { g_deg[i] = 0; g_cnt[i] = 0; }
    if (gtid < DOUT) { g_bnsum[gtid] = 0.f; g_bnsq[gtid] = 0.f; }

    if (b == 0) {
        if (t < 32) {
            const int* e32 = (const int*)ei;
            int bad = (e32[2 * ((long long)t * (EE / 32)) + 1] != 0);
            unsigned m = __ballot_sync(0xffffffffu, bad);
            const int* bb = (const int*)batch;
            int badb = (bb[2 * ((long long)t * (NN / 64)) + 1] != 0);
            unsigned mb = __ballot_sync(0xffffffffu, badb);
            if (t == 0) { g_flags[0] = m ? 1 : 0; g_flags[1] = mb ? 1 : 0; }
        }
        __syncthreads();
        if (t <= GG) {
            if (t == GG) g_seg[GG] = NN;
            else {
                int is32 = g_flags[1];
                int lo = 0, hi = NN;
                while (lo < hi) {
                    int mid = (lo + hi) >> 1;
                    if (fetch_idx(batch, mid, is32) < t) lo = mid + 1; else hi = mid;
                }
                g_seg[t] = lo;
            }
        }
    }
    if (b == NBLK - 1) {
        if (t < DIN) {
            float vt = 0.f;
            for (int i = 0; i < DOUT; i++) vt += W[i * DIN + t] * u[i];
            s_v[t] = vt;
        }
        __syncthreads();
        if (t == 0) {
            float s = 0.f;
            for (int k = 0; k < DIN; k++) s += s_v[k] * s_v[k];
            s_scal[0] = sqrtf(s) + 1e-12f;
        }
        __syncthreads();
        if (t < DIN) s_v[t] = s_v[t] / s_scal[0];
        __syncthreads();
        if (t < DOUT) {
            float wv = 0.f;
            for (int j = 0; j < DIN; j++) wv += W[(long)t * DIN + j] * s_v[j];
            s_red[t] = u[t] * wv;
        }
        __syncthreads();
        if (t == 0) {
            float s = 0.f;
            for (int k = 0; k < DOUT; k++) s += s_red[k];
            s_scal[1] = 1.0f / s;
        }
        __syncthreads();
        if (t < DOUT) {
            float is = s_scal[1];
            int kmax = INC * (t / OUTC + 1);
            const float* wr = W + (long)t * DIN;
            float* wo = g_Wm + (long)t * DIN;
            for (int c = 0; c < DIN; c++) wo[c] = (c < kmax) ? wr[c] * is : 0.f;
        }
    }
    gridbar(NBLK);

    // ---- P1: degree histogram ----
    {
        int is32 = g_flags[0];
        for (int e = gtid; e < EE; e += NT)
            atomicAdd(&g_deg[fetch_idx(ei, e, is32)], 1);
    }
    gridbar(NBLK);

    // ---- P2: exclusive scan + dinv (block 0) ----
    if (b == 0) {
        int lane = t & 31, wid = t >> 5;
        int base = t * 8;
        int d[8], loc[8];
        int run = 0;
#pragma unroll
        for (int k = 0; k < 8; k++) { d[k] = g_deg[base + k]; loc[k] = run; run += d[k]; }
        int v = run;
#pragma unroll
        for (int o = 1; o < 32; o <<= 1) {
            int n = __shfl_up_sync(0xffffffffu, v, o);
            if (lane >= o) v += n;
        }
        if (lane == 31) s_int[wid] = v;
        __syncthreads();
        if (wid == 0) {
            int w = s_int[lane];
#pragma unroll
            for (int o = 1; o < 32; o <<= 1) {
                int n = __shfl_up_sync(0xffffffffu, w, o);
                if (lane >= o) w += n;
            }
            s_int[lane] = w;
        }
        __syncthreads();
        int warpoff = (wid > 0) ? s_int[wid - 1] : 0;
        int excl = warpoff + v - run;
#pragma unroll
        for (int k = 0; k < 8; k++) {
            g_offs[base + k] = excl + loc[k];
            g_dinv[base + k] = (d[k] > 0) ? rsqrtf((float)d[k]) : 0.f;
        }
        if (t == NTHR - 1) g_offs[NN] = warpoff + v;
    }
    gridbar(NBLK);

    // ---- P3: scatter edges + per-edge weights ----
    {
        int is32 = g_flags[0];
        for (int e = gtid; e < EE; e += NT) {
            int r = fetch_idx(ei, e, is32);
            int c = fetch_idx(ei, (long long)EE + e, is32);
            int pos = g_offs[r] + atomicAdd(&g_cnt[r], 1);
            g_col[pos] = c;
            g_wt[pos] = g_dinv[r] * g_dinv[c];
        }
    }
    gridbar(NBLK);

    // ---- P4: SpMM1 (Lx -> Hab cols 0..63) ----
    spmm_body(x, INC, g_Hab, 128, gtid >> 5, gtid & 31, NT / 32);
}

// ================= K2: SpMM2 (standalone, high occupancy) =================
__global__ void spmm_kernel(const float* __restrict__ in, int ldin,
                            float* __restrict__ out, int ldout) {
    int gtid = blockIdx.x * blockDim.x + threadIdx.x;
    int node = gtid >> 5;
    if (node >= NN) return;
    spmm_body(in, ldin, out, ldout, node, gtid & 31, NN);   // one node per warp (stride >= NN)
}

// ================= K3: GEMM H = [x|Hab] @ Wm^T + b, float4 LDS, fused BN1 stats =================
__global__ void gemm_kernel(const float* __restrict__ x, const float* __restrict__ bias) {
    __shared__ float As[16][64];
    __shared__ float Bs[16][64];
    __shared__ float ssum[16][68];
    __shared__ float ssq[16][68];
    int t  = threadIdx.x;                 // 256
    int tx = t & 15, ty = t >> 4;
    int m0 = blockIdx.x * 64;
    int n0 = blockIdx.y * 64;
    int kmax = 64 * (blockIdx.y + 1);     // block-lower-triangular mask
    int lm = t >> 2;
    int lk = (t & 3) * 4;
    float cr[4][4];
#pragma unroll
    for (int i = 0; i < 4; i++)
#pragma unroll
        for (int j = 0; j < 4; j++) cr[i][j] = 0.f;

    for (int k0 = 0; k0 < kmax; k0 += 16) {
        float4 av;
        if (k0 < 64) av = *(const float4*)(x + (long)(m0 + lm) * INC + k0 + lk);
        else         av = *(const float4*)(g_Hab + (long)(m0 + lm) * 128 + (k0 - 64) + lk);
        As[lk + 0][lm] = av.x; As[lk + 1][lm] = av.y; As[lk + 2][lm] = av.z; As[lk + 3][lm] = av.w;
        float4 bv = *(const float4*)(g_Wm + (long)(n0 + lm) * DIN + k0 + lk);
        Bs[lk + 0][lm] = bv.x; Bs[lk + 1][lm] = bv.y; Bs[lk + 2][lm] = bv.z; Bs[lk + 3][lm] = bv.w;
        __syncthreads();
#pragma unroll
        for (int kk = 0; kk < 16; kk++) {
            float4 a = *(const float4*)&As[kk][ty * 4];
            float4 bq = *(const float4*)&Bs[kk][tx * 4];
            cr[0][0] += a.x * bq.x; cr[0][1] += a.x * bq.y; cr[0][2] += a.x * bq.z; cr[0][3] += a.x * bq.w;
            cr[1][0] += a.y * bq.x; cr[1][1] += a.y * bq.y; cr[1][2] += a.y * bq.z; cr[1][3] += a.y * bq.w;
            cr[2][0] += a.z * bq.x; cr[2][1] += a.z * bq.y; cr[2][2] += a.z * bq.z; cr[2][3] += a.z * bq.w;
            cr[3][0] += a.w * bq.x; cr[3][1] += a.w * bq.y; cr[3][2] += a.w * bq.z; cr[3][3] += a.w * bq.w;
        }
        __syncthreads();
    }
    float psum[4] = {0, 0, 0, 0}, psq[4] = {0, 0, 0, 0};
#pragma unroll
    for (int j = 0; j < 4; j++) {
        int n = n0 + tx * 4 + j;
        float bj = bias[n];
#pragma unroll
        for (int i = 0; i < 4; i++) {
            int m = m0 + ty * 4 + i;
            float v = cr[i][j] + bj;
            g_H[(long)m * DOUT + n] = v;
            psum[j] += v; psq[j] += v * v;
        }
    }
#pragma unroll
    for (int j = 0; j < 4; j++) { ssum[ty][tx * 4 + j] = psum[j]; ssq[ty][tx * 4 + j] = psq[j]; }
    __syncthreads();
    if (t < 64) {
        float s = 0.f, q = 0.f;
#pragma unroll
        for (int yy = 0; yy < 16; yy++) { s += ssum[yy][t]; q += ssq[yy][t]; }
        atomicAdd(&g_bnsum[n0 + t], s);
        atomicAdd(&g_bnsq[n0 + t], q);
    }
}

// ================= K4 (PROFILED): pool partials — BN1 apply + sum/max per row-quarter ==========
__global__ void pool_kernel(const float* __restrict__ g1, const float* __restrict__ be1) {
    int g = blockIdx.x;                   // 64 graphs
    int q = blockIdx.y;                   // 4 row-quarters
    int j = threadIdx.x;                  // 192 channels
    float mu = g_bnsum[j] * (1.f / NN);
    float var = g_bnsq[j] * (1.f / NN) - mu * mu;
    float a = g1[j] * rsqrtf(var + BNEPS);
    float c = be1[j] - a * mu;
    int s0 = g_seg[g], e0 = g_seg[g + 1];
    float sum = 0.f, mx = -INFINITY;
#pragma unroll 4
    for (int r = s0 + q; r < e0; r += 4) {
        float v = a * g_H[(long)r * DOUT + j] + c;
        sum += v;
        mx = fmaxf(mx, v);
    }
    g_psum[(g * 4 + q) * DOUT + j] = sum;
    g_pmax[(g * 4 + q) * DOUT + j] = mx;
}

// ================= K5: head — combine partials, BN2, FC1-3, log_softmax (persistent 64) =======
__global__ void __launch_bounds__(D3, 1)
head_kernel(const float* __restrict__ g2, const float* __restrict__ be2,
            const float* __restrict__ w1, const float* __restrict__ b1,
            const float* __restrict__ w2, const float* __restrict__ b2,
            const float* __restrict__ w3, const float* __restrict__ b3,
            float* __restrict__ out) {
    __shared__ float xr[D3];
    __shared__ float f1[D2];
    __shared__ float f2[DOUT];
    int g = blockIdx.x, t = threadIdx.x;  // 64 x 576

    // combine pool partials -> Hg
    if (t < DOUT) {
        float ts = g_psum[(g * 4 + 0) * DOUT + t] + g_psum[(g * 4 + 1) * DOUT + t]
                 + g_psum[(g * 4 + 2) * DOUT + t] + g_psum[(g * 4 + 3) * DOUT + t];
        float tm = fmaxf(fmaxf(g_pmax[(g * 4 + 0) * DOUT + t], g_pmax[(g * 4 + 1) * DOUT + t]),
                         fmaxf(g_pmax[(g * 4 + 2) * DOUT + t], g_pmax[(g * 4 + 3) * DOUT + t]));
        float cnt = fmaxf((float)(g_seg[g + 1] - g_seg[g]), 1.f);
        g_Hg[g * D3 + t]            = ts / cnt;
        g_Hg[g * D3 + DOUT + t]     = ts;
        g_Hg[g * D3 + 2 * DOUT + t] = tm;
    }
    gridbar(GG);

    // BN2 (channel t over 64 graphs) -> normalized input for this graph
    {
        float s = 0.f, q = 0.f;
#pragma unroll 8
        for (int r = 0; r < GG; r++) {
            float v = g_Hg[r * D3 + t];
            s += v; q += v * v;
        }
        float mu = s * (1.f / GG);
        float var = q * (1.f / GG) - mu * mu;
        float a = g2[t] * rsqrtf(var + BNEPS);
        xr[t] = a * (g_Hg[g * D3 + t] - mu) + be2[t];
    }
    __syncthreads();
    if (t < D2) {
        float acc = b1[t];
        const float* wr = w1 + (long)t * D3;
#pragma unroll 4
        for (int k = 0; k < D3; k++) acc += xr[k] * wr[k];
        f1[t] = fmaxf(acc, 0.f);
    }
    __syncthreads();
    if (t < DOUT) {
        float acc = b2[t];
        const float* wr = w2 + (long)t * D2;
#pragma unroll 4
        for (int k = 0; k < D2; k++) acc += f1[k] * wr[k];
        f2[t] = fmaxf(acc, 0.f);
    }
    __syncthreads();
    if (t < 32) {
        float logit = -INFINITY;
        if (t < NCLS) {
            float acc = b3[t];
            const float* wr = w3 + t * DOUT;
            for (int k = 0; k < DOUT; k++) acc += f2[k] * wr[k];
            logit = acc;
        }
        float mx = logit;
#pragma unroll
        for (int o = 16; o > 0; o >>= 1) mx = fmaxf(mx, __shfl_xor_sync(0xffffffffu, mx, o));
        float ex = (t < NCLS) ? expf(logit - mx) : 0.f;
        float se = ex;
#pragma unroll
        for (int o = 16; o > 0; o >>= 1) se += __shfl_xor_sync(0xffffffffu, se, o);
        if (t < NCLS) out[g * NCLS + t] = logit - mx - logf(se);
    }
}

// ---------------- launch ----------------
extern "C" void kernel_launch(void* const* d_in, const int* in_sizes, int n_in,
                              void* d_out, int out_size) {
    const float* x      = (const float*)d_in[0];
    const void*  ei     = d_in[1];
    const void*  batch  = d_in[2];
    const float* W_orig = (const float*)d_in[3];
    const float* bb     = (const float*)d_in[4];
    const float* u      = (const float*)d_in[5];
    const float* bn1g   = (const float*)d_in[6];
    const float* bn1b   = (const float*)d_in[7];
    const float* bn2g   = (const float*)d_in[8];
    const float* bn2b   = (const float*)d_in[9];
    const float* w1     = (const float*)d_in[10];
    const float* b1     = (const float*)d_in[11];
    const float* w2     = (const float*)d_in[12];
    const float* b2     = (const float*)d_in[13];
    const float* w3     = (const float*)d_in[14];
    const float* b3     = (const float*)d_in[15];
    float* out = (float*)d_out;

    float* hab = nullptr;
    cudaGetSymbolAddress((void**)&hab, g_Hab);

    prep_kernel<<<NBLK, NTHR>>>(x, ei, batch, W_orig, u);              // 1 (incl SpMM1)
    spmm_kernel<<<NN * 32 / 256, 256>>>(hab, 128, hab + 64, 128);      // 2
    dim3 ggrid(NN / 64, DOUT / 64);
    gemm_kernel<<<ggrid, 256>>>(x, bb);                                // 3
    pool_kernel<<<dim3(GG, 4), DOUT>>>(bn1g, bn1b);                    // 4 (PROFILED)
    head_kernel<<<GG, D3>>>(bn2g, bn2b, w1, b1, w2, b2, w3, b3, out);  // 5
}

// round 13
// speedup vs baseline: 1.0811x; 1.0182x over previous
#include <cuda_runtime.h>
#include <cuda_bf16.h>
#include <math.h>

// ---------------- problem constants ----------------
#define NN    8192
#define EE    262144
#define INC   64
#define OUTC  64
#define GG    64
#define NCLS  10
#define DIN   192
#define DOUT  192
#define D3    576
#define D2    384
#define BNEPS 1e-5f

// ---------------- device scratch ----------------
__device__ int   g_flags[2];
__device__ int   g_deg[NN];
__device__ float g_dinv[NN];
__device__ int   g_offs[NN + 1];
__device__ int   g_rank[EE];          // edge's slot within its row (captured in degree pass)
__device__ int   g_col[EE];
__device__ float g_wt[EE];
__device__ float g_Hab[NN * 128];     // [Lx | L^2 x], ld=128
__device__ float g_H[NN * DOUT];
__device__ float g_Wm[DOUT * DIN];
__device__ float g_bnsum[DOUT];
__device__ float g_bnsq[DOUT];
__device__ int   g_seg[GG + 1];
__device__ float g_Hg[GG * D3];
__device__ float g_psum[GG * 8 * DOUT];
__device__ float g_pmax[GG * 8 * DOUT];
__device__ int   g_barcnt = 0;
__device__ volatile int g_bargen = 0;

__device__ __forceinline__ int fetch_idx(const void* p, long long i, int is32) {
    if (is32) return ((const int*)p)[i];
    return (int)(((const long long*)p)[i]);
}

// generation grid barrier (used only inside head: 64 co-resident blocks)
__device__ __forceinline__ void gridbar(int nblk) {
    __syncthreads();
    if (threadIdx.x == 0) {
        int gen = g_bargen;
        __threadfence();
        if (atomicAdd(&g_barcnt, 1) == nblk - 1) {
            g_barcnt = 0;
            __threadfence();
            g_bargen = gen + 1;
        } else {
            while (g_bargen == gen) { __nanosleep(32); }
        }
        __threadfence();
    }
    __syncthreads();
}

// ---------------- K1: init (zero + dtype flags + segment boundaries) ----------------
__global__ void init_kernel(const void* ei, const void* batch) {
    int tid = blockIdx.x * blockDim.x + threadIdx.x;
    for (int i = tid; i < NN; i += gridDim.x * blockDim.x) g_deg[i] = 0;
    if (tid < DOUT) { g_bnsum[tid] = 0.f; g_bnsq[tid] = 0.f; }
    if (blockIdx.x == 0) {
        if (threadIdx.x < 32) {
            int t = threadIdx.x;
            const int* e32 = (const int*)ei;
            int bad = (e32[2 * ((long long)t * (EE / 32)) + 1] != 0);
            unsigned m = __ballot_sync(0xffffffffu, bad);
            const int* bb = (const int*)batch;
            int badb = (bb[2 * ((long long)t * (NN / 64)) + 1] != 0);
            unsigned mb = __ballot_sync(0xffffffffu, badb);
            if (t == 0) { g_flags[0] = m ? 1 : 0; g_flags[1] = mb ? 1 : 0; }
        }
        __syncthreads();
        int g = threadIdx.x;
        if (g <= GG) {
            if (g == GG) g_seg[GG] = NN;
            else {
                int is32 = g_flags[1];
                int lo = 0, hi = NN;
                while (lo < hi) {
                    int mid = (lo + hi) >> 1;
                    if (fetch_idx(batch, mid, is32) < g) lo = mid + 1; else hi = mid;
                }
                g_seg[g] = lo;
            }
        }
    }
}

// ---------------- K2: degree histogram + edge rank capture ----------------
__global__ void degree_kernel(const void* ei) {
    int e = blockIdx.x * blockDim.x + threadIdx.x;
    if (e < EE) {
        int r = fetch_idx(ei, e, g_flags[0]);
        g_rank[e] = atomicAdd(&g_deg[r], 1);
    }
}

// ---------------- K3: block0 = scan+dinv; block1 = sigma+Wm ----------------
__global__ void scan_sigma_kernel(const float* __restrict__ W, const float* __restrict__ u) {
    if (blockIdx.x == 0) {
        __shared__ int stot[32];
        int t = threadIdx.x;                  // 1024
        int lane = t & 31, wid = t >> 5;
        int base = t * 8;
        int d[8], loc[8];
        int run = 0;
#pragma unroll
        for (int k = 0; k < 8; k++) { d[k] = g_deg[base + k]; loc[k] = run; run += d[k]; }
        int v = run;
#pragma unroll
        for (int o = 1; o < 32; o <<= 1) {
            int n = __shfl_up_sync(0xffffffffu, v, o);
            if (lane >= o) v += n;
        }
        if (lane == 31) stot[wid] = v;
        __syncthreads();
        if (wid == 0) {
            int w = stot[lane];
#pragma unroll
            for (int o = 1; o < 32; o <<= 1) {
                int n = __shfl_up_sync(0xffffffffu, w, o);
                if (lane >= o) w += n;
            }
            stot[lane] = w;
        }
        __syncthreads();
        int warpoff = (wid > 0) ? stot[wid - 1] : 0;
        int excl = warpoff + v - run;
#pragma unroll
        for (int k = 0; k < 8; k++) {
            g_offs[base + k] = excl + loc[k];
            g_dinv[base + k] = (d[k] > 0) ? rsqrtf((float)d[k]) : 0.f;
        }
        if (t == 1023) g_offs[NN] = warpoff + v;
    } else {
        __shared__ float s_v[DIN];
        __shared__ float s_red[DOUT];
        __shared__ float s_scal[2];
        int t = threadIdx.x;
        if (t < DIN) {
            float vt = 0.f;
            for (int i = 0; i < DOUT; i++) vt += W[i * DIN + t] * u[i];
            s_v[t] = vt;
        }
        __syncthreads();
        if (t == 0) {
            float s = 0.f;
            for (int k = 0; k < DIN; k++) s += s_v[k] * s_v[k];
            s_scal[0] = sqrtf(s) + 1e-12f;
        }
        __syncthreads();
        if (t < DIN) s_v[t] = s_v[t] / s_scal[0];
        __syncthreads();
        if (t < DOUT) {
            float wv = 0.f;
            for (int j = 0; j < DIN; j++) wv += W[(long)t * DIN + j] * s_v[j];
            s_red[t] = u[t] * wv;
        }
        __syncthreads();
        if (t == 0) {
            float s = 0.f;
            for (int k = 0; k < DOUT; k++) s += s_red[k];
            s_scal[1] = 1.0f / s;
        }
        __syncthreads();
        if (t < DOUT) {
            float is = s_scal[1];
            int kmax = INC * (t / OUTC + 1);
            const float* wr = W + (long)t * DIN;
            float* wo = g_Wm + (long)t * DIN;
            for (int c = 0; c < DIN; c++) wo[c] = (c < kmax) ? wr[c] * is : 0.f;
        }
    }
}

// ---------------- K4: scatter edges (atomic-free via precomputed rank) ----------------
__global__ void scatter_kernel(const void* ei) {
    int e = blockIdx.x * blockDim.x + threadIdx.x;
    if (e < EE) {
        int is32 = g_flags[0];
        int r = fetch_idx(ei, e, is32);
        int c = fetch_idx(ei, (long long)EE + e, is32);
        int pos = g_offs[r] + g_rank[e];
        g_col[pos] = c;
        g_wt[pos] = g_dinv[r] * g_dinv[c];
    }
}

// ---------------- K5/K6: SpMM  out = in - sum_e w_e in[col_e]  (warp per node) ----------------
__global__ void spmm_kernel(const float* __restrict__ in, int ldin,
                            float* __restrict__ out, int ldout) {
    int gtid = blockIdx.x * blockDim.x + threadIdx.x;
    int node = gtid >> 5;
    int lane = gtid & 31;
    if (node >= NN) return;
    int p = g_offs[node];
    int pe = g_offs[node + 1];
    float acc0 = 0.f, acc1 = 0.f;
    for (; p + 4 <= pe; p += 4) {
        int c0 = g_col[p], c1 = g_col[p + 1], c2 = g_col[p + 2], c3 = g_col[p + 3];
        float w0 = g_wt[p], w1 = g_wt[p + 1], w2 = g_wt[p + 2], w3 = g_wt[p + 3];
        const float* r0 = in + (long)c0 * ldin;
        const float* r1 = in + (long)c1 * ldin;
        const float* r2 = in + (long)c2 * ldin;
        const float* r3 = in + (long)c3 * ldin;
        acc0 += w0 * r0[lane] + w1 * r1[lane] + w2 * r2[lane] + w3 * r3[lane];
        acc1 += w0 * r0[lane + 32] + w1 * r1[lane + 32] + w2 * r2[lane + 32] + w3 * r3[lane + 32];
    }
    for (; p < pe; p++) {
        int c0 = g_col[p];
        float w0 = g_wt[p];
        const float* r0 = in + (long)c0 * ldin;
        acc0 += w0 * r0[lane];
        acc1 += w0 * r0[lane + 32];
    }
    const float* ri = in + (long)node * ldin;
    out[(long)node * ldout + lane]      = ri[lane]      - acc0;
    out[(long)node * ldout + lane + 32] = ri[lane + 32] - acc1;
}

// ---------------- K7: GEMM H = [x|Hab] @ Wm^T + b, kmax per n-tile, fused BN1 stats ----------
__global__ void gemm_kernel(const float* __restrict__ x, const float* __restrict__ bias) {
    __shared__ float As[16][64];
    __shared__ float Bs[16][64];
    __shared__ float ssum[16][68];
    __shared__ float ssq[16][68];
    int t  = threadIdx.x;                 // 256
    int tx = t & 15, ty = t >> 4;
    int m0 = blockIdx.x * 64;
    int n0 = blockIdx.y * 64;
    int kmax = 64 * (blockIdx.y + 1);
    int lm = t >> 2;
    int lk = (t & 3) * 4;
    float cr[4][4];
#pragma unroll
    for (int i = 0; i < 4; i++)
#pragma unroll
        for (int j = 0; j < 4; j++) cr[i][j] = 0.f;

    for (int k0 = 0; k0 < kmax; k0 += 16) {
        float4 av;
        if (k0 < 64) av = *(const float4*)(x + (long)(m0 + lm) * INC + k0 + lk);
        else         av = *(const float4*)(g_Hab + (long)(m0 + lm) * 128 + (k0 - 64) + lk);
        As[lk + 0][lm] = av.x; As[lk + 1][lm] = av.y; As[lk + 2][lm] = av.z; As[lk + 3][lm] = av.w;
        float4 bv = *(const float4*)(g_Wm + (long)(n0 + lm) * DIN + k0 + lk);
        Bs[lk + 0][lm] = bv.x; Bs[lk + 1][lm] = bv.y; Bs[lk + 2][lm] = bv.z; Bs[lk + 3][lm] = bv.w;
        __syncthreads();
#pragma unroll
        for (int kk = 0; kk < 16; kk++) {
            float4 a = *(const float4*)&As[kk][ty * 4];
            float4 bq = *(const float4*)&Bs[kk][tx * 4];
            cr[0][0] += a.x * bq.x; cr[0][1] += a.x * bq.y; cr[0][2] += a.x * bq.z; cr[0][3] += a.x * bq.w;
            cr[1][0] += a.y * bq.x; cr[1][1] += a.y * bq.y; cr[1][2] += a.y * bq.z; cr[1][3] += a.y * bq.w;
            cr[2][0] += a.z * bq.x; cr[2][1] += a.z * bq.y; cr[2][2] += a.z * bq.z; cr[2][3] += a.z * bq.w;
            cr[3][0] += a.w * bq.x; cr[3][1] += a.w * bq.y; cr[3][2] += a.w * bq.z; cr[3][3] += a.w * bq.w;
        }
        __syncthreads();
    }
    float psum[4] = {0, 0, 0, 0}, psq[4] = {0, 0, 0, 0};
#pragma unroll
    for (int j = 0; j < 4; j++) {
        int n = n0 + tx * 4 + j;
        float bj = bias[n];
#pragma unroll
        for (int i = 0; i < 4; i++) {
            int m = m0 + ty * 4 + i;
            float v = cr[i][j] + bj;
            g_H[(long)m * DOUT + n] = v;
            psum[j] += v; psq[j] += v * v;
        }
    }
#pragma unroll
    for (int j = 0; j < 4; j++) { ssum[ty][tx * 4 + j] = psum[j]; ssq[ty][tx * 4 + j] = psq[j]; }
    __syncthreads();
    if (t < 64) {
        float s = 0.f, q = 0.f;
#pragma unroll
        for (int yy = 0; yy < 16; yy++) { s += ssum[yy][t]; q += ssq[yy][t]; }
        atomicAdd(&g_bnsum[n0 + t], s);
        atomicAdd(&g_bnsq[n0 + t], q);
    }
}

// ---------------- K8: pool partials — BN1 apply + sum/max per row-eighth ----------------
__global__ void pool_kernel(const float* __restrict__ g1, const float* __restrict__ be1) {
    int g = blockIdx.x;                   // 64 graphs
    int q = blockIdx.y;                   // 8 row-eighths
    int j = threadIdx.x;                  // 192 channels
    float mu = g_bnsum[j] * (1.f / NN);
    float var = g_bnsq[j] * (1.f / NN) - mu * mu;
    float a = g1[j] * rsqrtf(var + BNEPS);
    float c = be1[j] - a * mu;
    int s0 = g_seg[g], e0 = g_seg[g + 1];
    float sum = 0.f, mx = -INFINITY;
#pragma unroll 4
    for (int r = s0 + q; r < e0; r += 8) {
        float v = a * g_H[(long)r * DOUT + j] + c;
        sum += v;
        mx = fmaxf(mx, v);
    }
    g_psum[(g * 8 + q) * DOUT + j] = sum;
    g_pmax[(g * 8 + q) * DOUT + j] = mx;
}

// ---------------- K9: head — combine partials, BN2, FC1-3, log_softmax ----------------
__global__ void __launch_bounds__(D3, 1)
head_kernel(const float* __restrict__ g2, const float* __restrict__ be2,
            const float* __restrict__ w1, const float* __restrict__ b1,
            const float* __restrict__ w2, const float* __restrict__ b2,
            const float* __restrict__ w3, const float* __restrict__ b3,
            float* __restrict__ out) {
    __shared__ float xr[D3];
    __shared__ float f1[D2];
    __shared__ float f2[DOUT];
    int g = blockIdx.x, t = threadIdx.x;  // 64 x 576

    if (t < DOUT) {
        float ts = 0.f, tm = -INFINITY;
#pragma unroll
        for (int q = 0; q < 8; q++) {
            ts += g_psum[(g * 8 + q) * DOUT + t];
            tm = fmaxf(tm, g_pmax[(g * 8 + q) * DOUT + t]);
        }
        float cnt = fmaxf((float)(g_seg[g + 1] - g_seg[g]), 1.f);
        g_Hg[g * D3 + t]            = ts / cnt;
        g_Hg[g * D3 + DOUT + t]     = ts;
        g_Hg[g * D3 + 2 * DOUT + t] = tm;
    }
    gridbar(GG);

    {
        float s = 0.f, q = 0.f;
#pragma unroll 8
        for (int r = 0; r < GG; r++) {
            float v = g_Hg[r * D3 + t];
            s += v; q += v * v;
        }
        float mu = s * (1.f / GG);
        float var = q * (1.f / GG) - mu * mu;
        float a = g2[t] * rsqrtf(var + BNEPS);
        xr[t] = a * (g_Hg[g * D3 + t] - mu) + be2[t];
    }
    __syncthreads();
    if (t < D2) {
        float acc = b1[t];
        const float* wr = w1 + (long)t * D3;
#pragma unroll 4
        for (int k = 0; k < D3; k++) acc += xr[k] * wr[k];
        f1[t] = fmaxf(acc, 0.f);
    }
    __syncthreads();
    if (t < DOUT) {
        float acc = b2[t];
        const float* wr = w2 + (long)t * D2;
#pragma unroll 4
        for (int k = 0; k < D2; k++) acc += f1[k] * wr[k];
        f2[t] = fmaxf(acc, 0.f);
    }
    __syncthreads();
    if (t < 32) {
        float logit = -INFINITY;
        if (t < NCLS) {
            float acc = b3[t];
            const float* wr = w3 + t * DOUT;
            for (int k = 0; k < DOUT; k++) acc += f2[k] * wr[k];
            logit = acc;
        }
        float mx = logit;
#pragma unroll
        for (int o = 16; o > 0; o >>= 1) mx = fmaxf(mx, __shfl_xor_sync(0xffffffffu, mx, o));
        float ex = (t < NCLS) ? expf(logit - mx) : 0.f;
        float se = ex;
#pragma unroll
        for (int o = 16; o > 0; o >>= 1) se += __shfl_xor_sync(0xffffffffu, se, o);
        if (t < NCLS) out[g * NCLS + t] = logit - mx - logf(se);
    }
}

// ---------------- launch ----------------
extern "C" void kernel_launch(void* const* d_in, const int* in_sizes, int n_in,
                              void* d_out, int out_size) {
    const float* x      = (const float*)d_in[0];
    const void*  ei     = d_in[1];
    const void*  batch  = d_in[2];
    const float* W_orig = (const float*)d_in[3];
    const float* bb     = (const float*)d_in[4];
    const float* u      = (const float*)d_in[5];
    const float* bn1g   = (const float*)d_in[6];
    const float* bn1b   = (const float*)d_in[7];
    const float* bn2g   = (const float*)d_in[8];
    const float* bn2b   = (const float*)d_in[9];
    const float* w1     = (const float*)d_in[10];
    const float* b1     = (const float*)d_in[11];
    const float* w2     = (const float*)d_in[12];
    const float* b2     = (const float*)d_in[13];
    const float* w3     = (const float*)d_in[14];
    const float* b3     = (const float*)d_in[15];
    float* out = (float*)d_out;

    float* hab = nullptr;
    cudaGetSymbolAddress((void**)&hab, g_Hab);

    init_kernel<<<64, 256>>>(ei, batch);                               // 1
    degree_kernel<<<EE / 256, 256>>>(ei);                              // 2
    scan_sigma_kernel<<<2, 1024>>>(W_orig, u);                         // 3
    scatter_kernel<<<EE / 256, 256>>>(ei);                             // 4
    spmm_kernel<<<NN * 32 / 256, 256>>>(x, INC, hab, 128);             // 5
    spmm_kernel<<<NN * 32 / 256, 256>>>(hab, 128, hab + 64, 128);      // 6
    dim3 ggrid(NN / 64, DOUT / 64);
    gemm_kernel<<<ggrid, 256>>>(x, bb);                                // 7
    pool_kernel<<<dim3(GG, 8), DOUT>>>(bn1g, bn1b);                    // 8
    head_kernel<<<GG, D3>>>(bn2g, bn2b, w1, b1, w2, b2, w3, b3, out);  // 9
}

// round 14
// speedup vs baseline: 1.1378x; 1.0524x over previous
#include <cuda_runtime.h>
#include <cuda_bf16.h>
#include <math.h>

// ---------------- problem constants ----------------
#define NN    8192
#define EE    262144
#define INC   64
#define OUTC  64
#define GG    64
#define NCLS  10
#define DIN   192
#define DOUT  192
#define D3    576
#define D2    384
#define BNEPS 1e-5f

// ---------------- device scratch ----------------
__device__ int   g_flags[2];
__device__ int   g_deg[NN];
__device__ float g_dinv[NN];
__device__ int   g_offs[NN + 1];
__device__ int   g_rank[EE];
__device__ int   g_col[EE];
__device__ float g_wt[EE];
__device__ float g_Hab[NN * 128];     // [Lx | L^2 x], ld=128
__device__ float g_H[NN * DOUT];
__device__ float g_Wm[DOUT * DIN];
__device__ float g_bnsum[DOUT];
__device__ float g_bnsq[DOUT];
__device__ int   g_seg[GG + 1];
__device__ float g_Hg[GG * D3];
__device__ float g_psum[GG * 8 * DOUT];
__device__ float g_pmax[GG * 8 * DOUT];
__device__ int   g_barcnt = 0;
__device__ volatile int g_bargen = 0;

__device__ __forceinline__ int fetch_idx(const void* p, long long i, int is32) {
    if (is32) return ((const int*)p)[i];
    return (int)(((const long long*)p)[i]);
}

// generation grid barrier (used only inside head: 64 co-resident blocks)
__device__ __forceinline__ void gridbar(int nblk) {
    __syncthreads();
    if (threadIdx.x == 0) {
        int gen = g_bargen;
        __threadfence();
        if (atomicAdd(&g_barcnt, 1) == nblk - 1) {
            g_barcnt = 0;
            __threadfence();
            g_bargen = gen + 1;
        } else {
            while (g_bargen == gen) { __nanosleep(32); }
        }
        __threadfence();
    }
    __syncthreads();
}

// ---------------- K1: init (zero + dtype flags + segment boundaries) ----------------
__global__ void init_kernel(const void* ei, const void* batch) {
    int tid = blockIdx.x * blockDim.x + threadIdx.x;
    for (int i = tid; i < NN; i += gridDim.x * blockDim.x) g_deg[i] = 0;
    if (tid < DOUT) { g_bnsum[tid] = 0.f; g_bnsq[tid] = 0.f; }
    if (blockIdx.x == 0) {
        if (threadIdx.x < 32) {
            int t = threadIdx.x;
            const int* e32 = (const int*)ei;
            int bad = (e32[2 * ((long long)t * (EE / 32)) + 1] != 0);
            unsigned m = __ballot_sync(0xffffffffu, bad);
            const int* bb = (const int*)batch;
            int badb = (bb[2 * ((long long)t * (NN / 64)) + 1] != 0);
            unsigned mb = __ballot_sync(0xffffffffu, badb);
            if (t == 0) { g_flags[0] = m ? 1 : 0; g_flags[1] = mb ? 1 : 0; }
        }
        __syncthreads();
        int g = threadIdx.x;
        if (g <= GG) {
            if (g == GG) g_seg[GG] = NN;
            else {
                int is32 = g_flags[1];
                int lo = 0, hi = NN;
                while (lo < hi) {
                    int mid = (lo + hi) >> 1;
                    if (fetch_idx(batch, mid, is32) < g) lo = mid + 1; else hi = mid;
                }
                g_seg[g] = lo;
            }
        }
    }
}

// ---------------- K2: degree histogram + edge rank capture ----------------
__global__ void degree_kernel(const void* ei) {
    int e = blockIdx.x * blockDim.x + threadIdx.x;
    if (e < EE) {
        int r = fetch_idx(ei, e, g_flags[0]);
        g_rank[e] = atomicAdd(&g_deg[r], 1);
    }
}

// ---------------- K3: block0 = scan+dinv; block1 = sigma+Wm ----------------
__global__ void scan_sigma_kernel(const float* __restrict__ W, const float* __restrict__ u) {
    if (blockIdx.x == 0) {
        __shared__ int stot[32];
        int t = threadIdx.x;
        int lane = t & 31, wid = t >> 5;
        int base = t * 8;
        int d[8], loc[8];
        int run = 0;
#pragma unroll
        for (int k = 0; k < 8; k++) { d[k] = g_deg[base + k]; loc[k] = run; run += d[k]; }
        int v = run;
#pragma unroll
        for (int o = 1; o < 32; o <<= 1) {
            int n = __shfl_up_sync(0xffffffffu, v, o);
            if (lane >= o) v += n;
        }
        if (lane == 31) stot[wid] = v;
        __syncthreads();
        if (wid == 0) {
            int w = stot[lane];
#pragma unroll
            for (int o = 1; o < 32; o <<= 1) {
                int n = __shfl_up_sync(0xffffffffu, w, o);
                if (lane >= o) w += n;
            }
            stot[lane] = w;
        }
        __syncthreads();
        int warpoff = (wid > 0) ? stot[wid - 1] : 0;
        int excl = warpoff + v - run;
#pragma unroll
        for (int k = 0; k < 8; k++) {
            g_offs[base + k] = excl + loc[k];
            g_dinv[base + k] = (d[k] > 0) ? rsqrtf((float)d[k]) : 0.f;
        }
        if (t == 1023) g_offs[NN] = warpoff + v;
    } else {
        __shared__ float s_v[DIN];
        __shared__ float s_red[DOUT];
        __shared__ float s_scal[2];
        int t = threadIdx.x;
        if (t < DIN) {
            float vt = 0.f;
            for (int i = 0; i < DOUT; i++) vt += W[i * DIN + t] * u[i];
            s_v[t] = vt;
        }
        __syncthreads();
        if (t == 0) {
            float s = 0.f;
            for (int k = 0; k < DIN; k++) s += s_v[k] * s_v[k];
            s_scal[0] = sqrtf(s) + 1e-12f;
        }
        __syncthreads();
        if (t < DIN) s_v[t] = s_v[t] / s_scal[0];
        __syncthreads();
        if (t < DOUT) {
            float wv = 0.f;
            for (int j = 0; j < DIN; j++) wv += W[(long)t * DIN + j] * s_v[j];
            s_red[t] = u[t] * wv;
        }
        __syncthreads();
        if (t == 0) {
            float s = 0.f;
            for (int k = 0; k < DOUT; k++) s += s_red[k];
            s_scal[1] = 1.0f / s;
        }
        __syncthreads();
        if (t < DOUT) {
            float is = s_scal[1];
            int kmax = INC * (t / OUTC + 1);
            const float* wr = W + (long)t * DIN;
            float* wo = g_Wm + (long)t * DIN;
            for (int c = 0; c < DIN; c++) wo[c] = (c < kmax) ? wr[c] * is : 0.f;
        }
    }
}

// ---------------- K4: scatter edges (atomic-free via precomputed rank) ----------------
__global__ void scatter_kernel(const void* ei) {
    int e = blockIdx.x * blockDim.x + threadIdx.x;
    if (e < EE) {
        int is32 = g_flags[0];
        int r = fetch_idx(ei, e, is32);
        int c = fetch_idx(ei, (long long)EE + e, is32);
        int pos = g_offs[r] + g_rank[e];
        g_col[pos] = c;
        g_wt[pos] = g_dinv[r] * g_dinv[c];
    }
}

// ---------------- K5/K6: SpMM  out = in - sum_e w_e in[col_e]  (warp per node) ----------------
__global__ void spmm_kernel(const float* __restrict__ in, int ldin,
                            float* __restrict__ out, int ldout) {
    int gtid = blockIdx.x * blockDim.x + threadIdx.x;
    int node = gtid >> 5;
    int lane = gtid & 31;
    if (node >= NN) return;
    int p = g_offs[node];
    int pe = g_offs[node + 1];
    float acc0 = 0.f, acc1 = 0.f;
    for (; p + 4 <= pe; p += 4) {
        int c0 = g_col[p], c1 = g_col[p + 1], c2 = g_col[p + 2], c3 = g_col[p + 3];
        float w0 = g_wt[p], w1 = g_wt[p + 1], w2 = g_wt[p + 2], w3 = g_wt[p + 3];
        const float* r0 = in + (long)c0 * ldin;
        const float* r1 = in + (long)c1 * ldin;
        const float* r2 = in + (long)c2 * ldin;
        const float* r3 = in + (long)c3 * ldin;
        acc0 += w0 * r0[lane] + w1 * r1[lane] + w2 * r2[lane] + w3 * r3[lane];
        acc1 += w0 * r0[lane + 32] + w1 * r1[lane + 32] + w2 * r2[lane + 32] + w3 * r3[lane + 32];
    }
    for (; p < pe; p++) {
        int c0 = g_col[p];
        float w0 = g_wt[p];
        const float* r0 = in + (long)c0 * ldin;
        acc0 += w0 * r0[lane];
        acc1 += w0 * r0[lane + 32];
    }
    const float* ri = in + (long)node * ldin;
    out[(long)node * ldout + lane]      = ri[lane]      - acc0;
    out[(long)node * ldout + lane + 32] = ri[lane + 32] - acc1;
}

// ---------------- K7: GEMM H = [x|Hab] @ Wm^T + b, kmax per n-tile, fused BN1 stats ----------
__global__ void gemm_kernel(const float* __restrict__ x, const float* __restrict__ bias) {
    __shared__ float As[16][64];
    __shared__ float Bs[16][64];
    __shared__ float ssum[16][68];
    __shared__ float ssq[16][68];
    int t  = threadIdx.x;                 // 256
    int tx = t & 15, ty = t >> 4;
    int m0 = blockIdx.x * 64;
    int n0 = blockIdx.y * 64;
    int kmax = 64 * (blockIdx.y + 1);
    int lm = t >> 2;
    int lk = (t & 3) * 4;
    float cr[4][4];
#pragma unroll
    for (int i = 0; i < 4; i++)
#pragma unroll
        for (int j = 0; j < 4; j++) cr[i][j] = 0.f;

    for (int k0 = 0; k0 < kmax; k0 += 16) {
        float4 av;
        if (k0 < 64) av = *(const float4*)(x + (long)(m0 + lm) * INC + k0 + lk);
        else         av = *(const float4*)(g_Hab + (long)(m0 + lm) * 128 + (k0 - 64) + lk);
        As[lk + 0][lm] = av.x; As[lk + 1][lm] = av.y; As[lk + 2][lm] = av.z; As[lk + 3][lm] = av.w;
        float4 bv = *(const float4*)(g_Wm + (long)(n0 + lm) * DIN + k0 + lk);
        Bs[lk + 0][lm] = bv.x; Bs[lk + 1][lm] = bv.y; Bs[lk + 2][lm] = bv.z; Bs[lk + 3][lm] = bv.w;
        __syncthreads();
#pragma unroll
        for (int kk = 0; kk < 16; kk++) {
            float4 a = *(const float4*)&As[kk][ty * 4];
            float4 bq = *(const float4*)&Bs[kk][tx * 4];
            cr[0][0] += a.x * bq.x; cr[0][1] += a.x * bq.y; cr[0][2] += a.x * bq.z; cr[0][3] += a.x * bq.w;
            cr[1][0] += a.y * bq.x; cr[1][1] += a.y * bq.y; cr[1][2] += a.y * bq.z; cr[1][3] += a.y * bq.w;
            cr[2][0] += a.z * bq.x; cr[2][1] += a.z * bq.y; cr[2][2] += a.z * bq.z; cr[2][3] += a.z * bq.w;
            cr[3][0] += a.w * bq.x; cr[3][1] += a.w * bq.y; cr[3][2] += a.w * bq.z; cr[3][3] += a.w * bq.w;
        }
        __syncthreads();
    }
    float psum[4] = {0, 0, 0, 0}, psq[4] = {0, 0, 0, 0};
#pragma unroll
    for (int j = 0; j < 4; j++) {
        int n = n0 + tx * 4 + j;
        float bj = bias[n];
#pragma unroll
        for (int i = 0; i < 4; i++) {
            int m = m0 + ty * 4 + i;
            float v = cr[i][j] + bj;
            g_H[(long)m * DOUT + n] = v;
            psum[j] += v; psq[j] += v * v;
        }
    }
#pragma unroll
    for (int j = 0; j < 4; j++) { ssum[ty][tx * 4 + j] = psum[j]; ssq[ty][tx * 4 + j] = psq[j]; }
    __syncthreads();
    if (t < 64) {
        float s = 0.f, q = 0.f;
#pragma unroll
        for (int yy = 0; yy < 16; yy++) { s += ssum[yy][t]; q += ssq[yy][t]; }
        atomicAdd(&g_bnsum[n0 + t], s);
        atomicAdd(&g_bnsq[n0 + t], q);
    }
}

// ---------------- K8: pool partials — BN1 apply + sum/max per row-eighth ----------------
__global__ void pool_kernel(const float* __restrict__ g1, const float* __restrict__ be1) {
    int g = blockIdx.x;
    int q = blockIdx.y;                   // 8 row-eighths
    int j = threadIdx.x;                  // 192 channels
    float mu = g_bnsum[j] * (1.f / NN);
    float var = g_bnsq[j] * (1.f / NN) - mu * mu;
    float a = g1[j] * rsqrtf(var + BNEPS);
    float c = be1[j] - a * mu;
    int s0 = g_seg[g], e0 = g_seg[g + 1];
    float sum = 0.f, mx = -INFINITY;
#pragma unroll 4
    for (int r = s0 + q; r < e0; r += 8) {
        float v = a * g_H[(long)r * DOUT + j] + c;
        sum += v;
        mx = fmaxf(mx, v);
    }
    g_psum[(g * 8 + q) * DOUT + j] = sum;
    g_pmax[(g * 8 + q) * DOUT + j] = mx;
}

// ---------------- K9: head — combine, BN2, FC1-3 (warp-per-row, coalesced weights) ----------
__global__ void __launch_bounds__(512, 1)
head_kernel(const float* __restrict__ g2, const float* __restrict__ be2,
            const float* __restrict__ w1, const float* __restrict__ b1,
            const float* __restrict__ w2, const float* __restrict__ b2,
            const float* __restrict__ w3, const float* __restrict__ b3,
            float* __restrict__ out) {
    __shared__ float xr[D3];
    __shared__ float f1[D2];
    __shared__ float f2[DOUT];
    int g = blockIdx.x, t = threadIdx.x;  // 64 x 512
    int w = t >> 5, lane = t & 31;        // 16 warps

    // combine pool partials -> Hg
    if (t < DOUT) {
        float ts = 0.f, tm = -INFINITY;
#pragma unroll
        for (int q = 0; q < 8; q++) {
            ts += g_psum[(g * 8 + q) * DOUT + t];
            tm = fmaxf(tm, g_pmax[(g * 8 + q) * DOUT + t]);
        }
        float cnt = fmaxf((float)(g_seg[g + 1] - g_seg[g]), 1.f);
        g_Hg[g * D3 + t]            = ts / cnt;
        g_Hg[g * D3 + DOUT + t]     = ts;
        g_Hg[g * D3 + 2 * DOUT + t] = tm;
    }
    gridbar(GG);

    // BN2: channel stats over 64 graphs; normalized input for this graph
    for (int ch = t; ch < D3; ch += 512) {
        float s = 0.f, q = 0.f;
#pragma unroll 8
        for (int r = 0; r < GG; r++) {
            float v = g_Hg[r * D3 + ch];
            s += v; q += v * v;
        }
        float mu = s * (1.f / GG);
        float var = q * (1.f / GG) - mu * mu;
        float a = g2[ch] * rsqrtf(var + BNEPS);
        xr[ch] = a * (g_Hg[g * D3 + ch] - mu) + be2[ch];
    }
    __syncthreads();

    // FC1: warp per output row, lanes split K (coalesced w1 reads)
    for (int r = w; r < D2; r += 16) {
        const float* wr = w1 + (long)r * D3;
        float acc = 0.f;
#pragma unroll
        for (int k = lane; k < D3; k += 32) acc += xr[k] * wr[k];
#pragma unroll
        for (int o = 16; o > 0; o >>= 1) acc += __shfl_xor_sync(0xffffffffu, acc, o);
        if (lane == 0) f1[r] = fmaxf(acc + b1[r], 0.f);
    }
    __syncthreads();

    // FC2: warp per output row
    for (int r = w; r < DOUT; r += 16) {
        const float* wr = w2 + (long)r * D2;
        float acc = 0.f;
#pragma unroll
        for (int k = lane; k < D2; k += 32) acc += f1[k] * wr[k];
#pragma unroll
        for (int o = 16; o > 0; o >>= 1) acc += __shfl_xor_sync(0xffffffffu, acc, o);
        if (lane == 0) f2[r] = fmaxf(acc + b2[r], 0.f);
    }
    __syncthreads();

    // FC3: warps 0..9 each compute one logit (coalesced w3 reads), warp 15 does softmax
    __shared__ float logits[16];
    if (w < NCLS) {
        const float* wr = w3 + w * DOUT;
        float acc = 0.f;
#pragma unroll
        for (int k = lane; k < DOUT; k += 32) acc += f2[k] * wr[k];
#pragma unroll
        for (int o = 16; o > 0; o >>= 1) acc += __shfl_xor_sync(0xffffffffu, acc, o);
        if (lane == 0) logits[w] = acc + b3[w];
    }
    __syncthreads();
    if (t < 32) {
        float logit = (t < NCLS) ? logits[t] : -INFINITY;
        float mx = logit;
#pragma unroll
        for (int o = 16; o > 0; o >>= 1) mx = fmaxf(mx, __shfl_xor_sync(0xffffffffu, mx, o));
        float ex = (t < NCLS) ? expf(logit - mx) : 0.f;
        float se = ex;
#pragma unroll
        for (int o = 16; o > 0; o >>= 1) se += __shfl_xor_sync(0xffffffffu, se, o);
        if (t < NCLS) out[g * NCLS + t] = logit - mx - logf(se);
    }
}

// ---------------- launch ----------------
extern "C" void kernel_launch(void* const* d_in, const int* in_sizes, int n_in,
                              void* d_out, int out_size) {
    const float* x      = (const float*)d_in[0];
    const void*  ei     = d_in[1];
    const void*  batch  = d_in[2];
    const float* W_orig = (const float*)d_in[3];
    const float* bb     = (const float*)d_in[4];
    const float* u      = (const float*)d_in[5];
    const float* bn1g   = (const float*)d_in[6];
    const float* bn1b   = (const float*)d_in[7];
    const float* bn2g   = (const float*)d_in[8];
    const float* bn2b   = (const float*)d_in[9];
    const float* w1     = (const float*)d_in[10];
    const float* b1     = (const float*)d_in[11];
    const float* w2     = (const float*)d_in[12];
    const float* b2     = (const float*)d_in[13];
    const float* w3     = (const float*)d_in[14];
    const float* b3     = (const float*)d_in[15];
    float* out = (float*)d_out;

    float* hab = nullptr;
    cudaGetSymbolAddress((void**)&hab, g_Hab);

    init_kernel<<<64, 256>>>(ei, batch);
    degree_kernel<<<EE / 256, 256>>>(ei);
    scan_sigma_kernel<<<2, 1024>>>(W_orig, u);
    scatter_kernel<<<EE / 256, 256>>>(ei);
    spmm_kernel<<<NN * 32 / 256, 256>>>(x, INC, hab, 128);
    spmm_kernel<<<NN * 32 / 256, 256>>>(hab, 128, hab + 64, 128);
    dim3 ggrid(NN / 64, DOUT / 64);
    gemm_kernel<<<ggrid, 256>>>(x, bb);
    pool_kernel<<<dim3(GG, 8), DOUT>>>(bn1g, bn1b);
    head_kernel<<<GG, 512>>>(bn2g, bn2b, w1, b1, w2, b2, w3, b3, out);
}

// round 16
// speedup vs baseline: 1.8206x; 1.6001x over previous
#include <cuda_runtime.h>
#include <cuda_bf16.h>
#include <math.h>

// ---------------- problem constants ----------------
#define NN    8192
#define EE    262144
#define INC   64
#define OUTC  64
#define GG    64
#define NCLS  10
#define DIN   192
#define DOUT  192
#define D3    576
#define D2    384
#define BNEPS 1e-5f

#define FBLK  296                 // 2 blocks/SM x 148
#define FTHR  512
#define FNT   (FBLK * FTHR)       // 151552

// ---------------- device scratch ----------------
__device__ int   g_flags[2];
__device__ int   g_deg[NN];
__device__ float g_dinv[NN];
__device__ int   g_offs[NN + 1];
__device__ int   g_rank[EE];
__device__ int   g_col[EE];
__device__ float g_wt[EE];
__device__ float g_Hab[NN * 128];     // [Lx | L^2 x], ld=128
__device__ float g_H[NN * DOUT];
__device__ float g_Wm[DOUT * DIN];
__device__ float g_bnsum[DOUT];
__device__ float g_bnsq[DOUT];
__device__ int   g_seg[GG + 1];
__device__ float g_Hg[GG * D3];
__device__ int   g_barcnt = 0;
__device__ volatile int g_bargen = 0;

__device__ __forceinline__ int fetch_idx(const void* p, long long i, int is32) {
    if (is32) return ((const int*)p)[i];
    return (int)(((const long long*)p)[i]);
}

// generation grid barrier; requires all nblk blocks co-resident
__device__ __forceinline__ void gridbar(int nblk) {
    __syncthreads();
    if (threadIdx.x == 0) {
        int gen = g_bargen;
        __threadfence();
        if (atomicAdd(&g_barcnt, 1) == nblk - 1) {
            g_barcnt = 0;
            __threadfence();
            g_bargen = gen + 1;
        } else {
            while (g_bargen == gen) { __nanosleep(32); }
        }
        __threadfence();
    }
    __syncthreads();
}

// SpMM body: out = in - sum_e w_e in[col_e], warp per node, stride nwarp
__device__ __forceinline__ void spmm_body(const float* __restrict__ in, int ldin,
                                          float* __restrict__ out, int ldout,
                                          int warp, int lane, int nwarp) {
    for (int node = warp; node < NN; node += nwarp) {
        int p = g_offs[node];
        int pe = g_offs[node + 1];
        float acc0 = 0.f, acc1 = 0.f;
        for (; p + 4 <= pe; p += 4) {
            int c0 = g_col[p], c1 = g_col[p + 1], c2 = g_col[p + 2], c3 = g_col[p + 3];
            float w0 = g_wt[p], w1 = g_wt[p + 1], w2 = g_wt[p + 2], w3 = g_wt[p + 3];
            const float* r0 = in + (long)c0 * ldin;
            const float* r1 = in + (long)c1 * ldin;
            const float* r2 = in + (long)c2 * ldin;
            const float* r3 = in + (long)c3 * ldin;
            acc0 += w0 * r0[lane] + w1 * r1[lane] + w2 * r2[lane] + w3 * r3[lane];
            acc1 += w0 * r0[lane + 32] + w1 * r1[lane + 32] + w2 * r2[lane + 32] + w3 * r3[lane + 32];
        }
        for (; p < pe; p++) {
            int c0 = g_col[p];
            float w0 = g_wt[p];
            const float* r0 = in + (long)c0 * ldin;
            acc0 += w0 * r0[lane];
            acc1 += w0 * r0[lane + 32];
        }
        const float* ri = in + (long)node * ldin;
        out[(long)node * ldout + lane]      = ri[lane]      - acc0;
        out[(long)node * ldout + lane + 32] = ri[lane + 32] - acc1;
    }
}

// ================= K1: persistent front, full occupancy (2 blocks/SM x 512) =================
__global__ void __launch_bounds__(FTHR, 2)
front_kernel(const float* __restrict__ x, const void* ei, const void* batch,
             const float* __restrict__ W, const float* __restrict__ u) {
    __shared__ int   s_int[32];
    __shared__ float s_v[DIN];
    __shared__ float s_red[DOUT];
    __shared__ float s_scal[2];

    int b = blockIdx.x, t = threadIdx.x;
    int gtid = b * FTHR + t;

    // ---- P0: zero + flags/segments (block 0) + sigma/Wm (block FBLK-1) ----
    for (int i = gtid; i < NN; i += FNT) g_deg[i] = 0;
    if (gtid < DOUT) { g_bnsum[gtid] = 0.f; g_bnsq[gtid] = 0.f; }

    if (b == 0) {
        if (t < 32) {
            // dtype probes: int64 view, high word of spread elements (in-bounds either way)
            const int* e32 = (const int*)ei;
            int bad = (e32[2 * ((long long)t * (EE / 32)) + 1] != 0);
            unsigned m = __ballot_sync(0xffffffffu, bad);
            const int* bb = (const int*)batch;
            int badb = (bb[2 * ((long long)t * (NN / 64)) + 1] != 0);
            unsigned mb = __ballot_sync(0xffffffffu, badb);
            if (t == 0) { g_flags[0] = m ? 1 : 0; g_flags[1] = mb ? 1 : 0; }
        }
        __syncthreads();
        if (t <= GG) {
            if (t == GG) g_seg[GG] = NN;
            else {
                int is32 = g_flags[1];
                int lo = 0, hi = NN;
                while (lo < hi) {
                    int mid = (lo + hi) >> 1;
                    if (fetch_idx(batch, mid, is32) < t) lo = mid + 1; else hi = mid;
                }
                g_seg[t] = lo;
            }
        }
    }
    if (b == FBLK - 1) {
        // spectral sigma (one power-iteration step) + masked scaled Wm
        if (t < DIN) {
            float vt = 0.f;
            for (int i = 0; i < DOUT; i++) vt += W[i * DIN + t] * u[i];
            s_v[t] = vt;
        }
        __syncthreads();
        if (t == 0) {
            float s = 0.f;
            for (int k = 0; k < DIN; k++) s += s_v[k] * s_v[k];
            s_scal[0] = sqrtf(s) + 1e-12f;
        }
        __syncthreads();
        if (t < DIN) s_v[t] = s_v[t] / s_scal[0];
        __syncthreads();
        if (t < DOUT) {
            float wv = 0.f;
            for (int j = 0; j < DIN; j++) wv += W[(long)t * DIN + j] * s_v[j];
            s_red[t] = u[t] * wv;
        }
        __syncthreads();
        if (t == 0) {
            float s = 0.f;
            for (int k = 0; k < DOUT; k++) s += s_red[k];
            s_scal[1] = 1.0f / s;
        }
        __syncthreads();
        if (t < DOUT) {
            float is = s_scal[1];
            int kmax = INC * (t / OUTC + 1);
            const float* wr = W + (long)t * DIN;
            float* wo = g_Wm + (long)t * DIN;
            for (int c = 0; c < DIN; c++) wo[c] = (c < kmax) ? wr[c] * is : 0.f;
        }
    }
    gridbar(FBLK);

    // ---- P1: degree histogram + rank capture ----
    {
        int is32 = g_flags[0];
        for (int e = gtid; e < EE; e += FNT)
            g_rank[e] = atomicAdd(&g_deg[fetch_idx(ei, e, is32)], 1);
    }
    gridbar(FBLK);

    // ---- P2: exclusive scan + dinv (block 0; 512 threads x 16 elems) ----
    if (b == 0) {
        int lane = t & 31, wid = t >> 5;
        int base = t * 16;
        int d[16], loc[16];
        int run = 0;
#pragma unroll
        for (int k = 0; k < 16; k++) { d[k] = g_deg[base + k]; loc[k] = run; run += d[k]; }
        int v = run;
#pragma unroll
        for (int o = 1; o < 32; o <<= 1) {
            int n = __shfl_up_sync(0xffffffffu, v, o);
            if (lane >= o) v += n;
        }
        if (lane == 31) s_int[wid] = v;
        __syncthreads();
        if (wid == 0 && lane < 16) {
            int w = s_int[lane];
#pragma unroll
            for (int o = 1; o < 16; o <<= 1) {
                int n = __shfl_up_sync(0x0000ffffu, w, o);
                if (lane >= o) w += n;
            }
            s_int[lane] = w;
        }
        __syncthreads();
        int warpoff = (wid > 0) ? s_int[wid - 1] : 0;
        int excl = warpoff + v - run;
#pragma unroll
        for (int k = 0; k < 16; k++) {
            g_offs[base + k] = excl + loc[k];
            g_dinv[base + k] = (d[k] > 0) ? rsqrtf((float)d[k]) : 0.f;
        }
        if (t == FTHR - 1) g_offs[NN] = warpoff + v;
    }
    gridbar(FBLK);

    // ---- P3: scatter edges (atomic-free) ----
    {
        int is32 = g_flags[0];
        for (int e = gtid; e < EE; e += FNT) {
            int r = fetch_idx(ei, e, is32);
            int c = fetch_idx(ei, (long long)EE + e, is32);
            int pos = g_offs[r] + g_rank[e];
            g_col[pos] = c;
            g_wt[pos] = g_dinv[r] * g_dinv[c];
        }
    }
    gridbar(FBLK);

    // ---- P4: SpMM1 (x -> Hab cols 0..63) ----
    spmm_body(x, INC, g_Hab, 128, gtid >> 5, gtid & 31, FNT / 32);
    gridbar(FBLK);

    // ---- P5: SpMM2 (Hab cols 0..63 -> cols 64..127) ----
    spmm_body(g_Hab, 128, g_Hab + 64, 128, gtid >> 5, gtid & 31, FNT / 32);
}

// ================= K2: GEMM H = [x|Hab] @ Wm^T + b, kmax per n-tile, fused BN1 stats =========
__global__ void gemm_kernel(const float* __restrict__ x, const float* __restrict__ bias) {
    __shared__ float As[16][64];
    __shared__ float Bs[16][64];
    __shared__ float ssum[16][68];
    __shared__ float ssq[16][68];
    int t  = threadIdx.x;                 // 256
    int tx = t & 15, ty = t >> 4;
    int m0 = blockIdx.x * 64;
    int n0 = blockIdx.y * 64;
    int kmax = 64 * (blockIdx.y + 1);
    int lm = t >> 2;
    int lk = (t & 3) * 4;
    float cr[4][4];
#pragma unroll
    for (int i = 0; i < 4; i++)
#pragma unroll
        for (int j = 0; j < 4; j++) cr[i][j] = 0.f;

    for (int k0 = 0; k0 < kmax; k0 += 16) {
        float4 av;
        if (k0 < 64) av = *(const float4*)(x + (long)(m0 + lm) * INC + k0 + lk);
        else         av = *(const float4*)(g_Hab + (long)(m0 + lm) * 128 + (k0 - 64) + lk);
        As[lk + 0][lm] = av.x; As[lk + 1][lm] = av.y; As[lk + 2][lm] = av.z; As[lk + 3][lm] = av.w;
        float4 bv = *(const float4*)(g_Wm + (long)(n0 + lm) * DIN + k0 + lk);
        Bs[lk + 0][lm] = bv.x; Bs[lk + 1][lm] = bv.y; Bs[lk + 2][lm] = bv.z; Bs[lk + 3][lm] = bv.w;
        __syncthreads();
#pragma unroll
        for (int kk = 0; kk < 16; kk++) {
            float4 a = *(const float4*)&As[kk][ty * 4];
            float4 bq = *(const float4*)&Bs[kk][tx * 4];
            cr[0][0] += a.x * bq.x; cr[0][1] += a.x * bq.y; cr[0][2] += a.x * bq.z; cr[0][3] += a.x * bq.w;
            cr[1][0] += a.y * bq.x; cr[1][1] += a.y * bq.y; cr[1][2] += a.y * bq.z; cr[1][3] += a.y * bq.w;
            cr[2][0] += a.z * bq.x; cr[2][1] += a.z * bq.y; cr[2][2] += a.z * bq.z; cr[2][3] += a.z * bq.w;
            cr[3][0] += a.w * bq.x; cr[3][1] += a.w * bq.y; cr[3][2] += a.w * bq.z; cr[3][3] += a.w * bq.w;
        }
        __syncthreads();
    }
    float psum[4] = {0, 0, 0, 0}, psq[4] = {0, 0, 0, 0};
#pragma unroll
    for (int j = 0; j < 4; j++) {
        int n = n0 + tx * 4 + j;
        float bj = bias[n];
#pragma unroll
        for (int i = 0; i < 4; i++) {
            int m = m0 + ty * 4 + i;
            float v = cr[i][j] + bj;
            g_H[(long)m * DOUT + n] = v;
            psum[j] += v; psq[j] += v * v;
        }
    }
#pragma unroll
    for (int j = 0; j < 4; j++) { ssum[ty][tx * 4 + j] = psum[j]; ssq[ty][tx * 4 + j] = psq[j]; }
    __syncthreads();
    if (t < 64) {
        float s = 0.f, q = 0.f;
#pragma unroll
        for (int yy = 0; yy < 16; yy++) { s += ssum[yy][t]; q += ssq[yy][t]; }
        atomicAdd(&g_bnsum[n0 + t], s);
        atomicAdd(&g_bnsq[n0 + t], q);
    }
}

// ================= K3: pool + head (64 blocks x 512, one grid bar) =================
__global__ void __launch_bounds__(512, 1)
pool_head_kernel(const float* __restrict__ g1, const float* __restrict__ be1,
                 const float* __restrict__ g2, const float* __restrict__ be2,
                 const float* __restrict__ w1, const float* __restrict__ b1,
                 const float* __restrict__ w2, const float* __restrict__ b2,
                 const float* __restrict__ w3, const float* __restrict__ b3,
                 float* __restrict__ out) {
    __shared__ float xr[D3];
    __shared__ float f1[D2];
    __shared__ float f2[DOUT];
    __shared__ float ps[2][DOUT], pm[2][DOUT];
    __shared__ float logits[16];
    int g = blockIdx.x, t = threadIdx.x;  // 64 x 512
    int w = t >> 5, lane = t & 31;        // 16 warps

    // ---- pool: BN1 apply + avg|sum|max for this block's graph ----
    {
        int j = t % DOUT, y = t / DOUT;   // y in 0..2 (y==2 partially idle)
        int s0 = g_seg[g], e0 = g_seg[g + 1];
        if (y < 2) {
            float mu = g_bnsum[j] * (1.f / NN);
            float var = g_bnsq[j] * (1.f / NN) - mu * mu;
            float a = g1[j] * rsqrtf(var + BNEPS);
            float c = be1[j] - a * mu;
            float sum = 0.f, mx = -INFINITY;
            for (int r = s0 + y; r < e0; r += 2) {
                float v = a * g_H[(long)r * DOUT + j] + c;
                sum += v;
                mx = fmaxf(mx, v);
            }
            ps[y][j] = sum; pm[y][j] = mx;
        }
        __syncthreads();
        if (t < DOUT) {
            float ts = ps[0][t] + ps[1][t];
            float tm = fmaxf(pm[0][t], pm[1][t]);
            float cnt = fmaxf((float)(e0 - s0), 1.f);
            g_Hg[g * D3 + t]            = ts / cnt;
            g_Hg[g * D3 + DOUT + t]     = ts;
            g_Hg[g * D3 + 2 * DOUT + t] = tm;
        }
    }
    gridbar(GG);

    // ---- BN2: channel stats over 64 graphs; normalized input for this graph ----
    for (int ch = t; ch < D3; ch += 512) {
        float s = 0.f, q = 0.f;
#pragma unroll 8
        for (int r = 0; r < GG; r++) {
            float v = g_Hg[r * D3 + ch];
            s += v; q += v * v;
        }
        float mu = s * (1.f / GG);
        float var = q * (1.f / GG) - mu * mu;
        float a = g2[ch] * rsqrtf(var + BNEPS);
        xr[ch] = a * (g_Hg[g * D3 + ch] - mu) + be2[ch];
    }
    __syncthreads();

    // ---- FC1: warp per output row, coalesced weights ----
    for (int r = w; r < D2; r += 16) {
        const float* wr = w1 + (long)r * D3;
        float acc = 0.f;
#pragma unroll
        for (int k = lane; k < D3; k += 32) acc += xr[k] * wr[k];
#pragma unroll
        for (int o = 16; o > 0; o >>= 1) acc += __shfl_xor_sync(0xffffffffu, acc, o);
        if (lane == 0) f1[r] = fmaxf(acc + b1[r], 0.f);
    }
    __syncthreads();

    // ---- FC2 ----
    for (int r = w; r < DOUT; r += 16) {
        const float* wr = w2 + (long)r * D2;
        float acc = 0.f;
#pragma unroll
        for (int k = lane; k < D2; k += 32) acc += f1[k] * wr[k];
#pragma unroll
        for (int o = 16; o > 0; o >>= 1) acc += __shfl_xor_sync(0xffffffffu, acc, o);
        if (lane == 0) f2[r] = fmaxf(acc + b2[r], 0.f);
    }
    __syncthreads();

    // ---- FC3 + log_softmax ----
    if (w < NCLS) {
        const float* wr = w3 + w * DOUT;
        float acc = 0.f;
#pragma unroll
        for (int k = lane; k < DOUT; k += 32) acc += f2[k] * wr[k];
#pragma unroll
        for (int o = 16; o > 0; o >>= 1) acc += __shfl_xor_sync(0xffffffffu, acc, o);
        if (lane == 0) logits[w] = acc + b3[w];
    }
    __syncthreads();
    if (t < 32) {
        float logit = (t < NCLS) ? logits[t] : -INFINITY;
        float mx = logit;
#pragma unroll
        for (int o = 16; o > 0; o >>= 1) mx = fmaxf(mx, __shfl_xor_sync(0xffffffffu, mx, o));
        float ex = (t < NCLS) ? expf(logit - mx) : 0.f;
        float se = ex;
#pragma unroll
        for (int o = 16; o > 0; o >>= 1) se += __shfl_xor_sync(0xffffffffu, se, o);
        if (t < NCLS) out[g * NCLS + t] = logit - mx - logf(se);
    }
}

// ---------------- launch ----------------
extern "C" void kernel_launch(void* const* d_in, const int* in_sizes, int n_in,
                              void* d_out, int out_size) {
    const float* x      = (const float*)d_in[0];
    const void*  ei     = d_in[1];
    const void*  batch  = d_in[2];
    const float* W_orig = (const float*)d_in[3];
    const float* bb     = (const float*)d_in[4];
    const float* u      = (const float*)d_in[5];
    const float* bn1g   = (const float*)d_in[6];
    const float* bn1b   = (const float*)d_in[7];
    const float* bn2g   = (const float*)d_in[8];
    const float* bn2b   = (const float*)d_in[9];
    const float* w1     = (const float*)d_in[10];
    const float* b1     = (const float*)d_in[11];
    const float* w2     = (const float*)d_in[12];
    const float* b2     = (const float*)d_in[13];
    const float* w3     = (const float*)d_in[14];
    const float* b3     = (const float*)d_in[15];
    float* out = (float*)d_out;

    front_kernel<<<FBLK, FTHR>>>(x, ei, batch, W_orig, u);
    dim3 ggrid(NN / 64, DOUT / 64);
    gemm_kernel<<<ggrid, 256>>>(x, bb);
    pool_head_kernel<<<GG, 512>>>(bn1g, bn1b, bn2g, bn2b,
                                  w1, b1, w2, b2, w3, b3, out);
}